// round 15
// baseline (speedup 1.0000x reference)
#include <cuda_runtime.h>
#include <cuda_bf16.h>
#include <math.h>

#define SL 50
#define TL 50
#define BA 16
#define HID 1024
#define HD2 512
#define NL 4
#define VOUT 32000

__device__ __align__(16) float g_encx [SL*BA*HID];
__device__ __align__(16) float g_ency [SL*BA*HID];
__device__ __align__(16) float g_encxg[SL*BA*4096];
__device__ __align__(16) float g_enchA[2*BA*HD2];
__device__ __align__(16) float g_enchB[2*BA*HD2];
__device__ __align__(16) float g_encc [2*BA*HD2];
__device__ __align__(16) float g_h0   [NL*BA*HID];
__device__ __align__(16) float g_c0   [NL*BA*HID];
__device__ __align__(16) float g_demb [TL*BA*HID];
__device__ __align__(16) float g_pre0 [TL*BA*4096];
__device__ __align__(16) float g_dhA  [NL*BA*HID];
__device__ __align__(16) float g_dhB  [NL*BA*HID];
__device__ __align__(16) float g_dc   [NL*BA*HID];
__device__ __align__(16) float g_htl  [BA*HID];
__device__ __align__(16) float g_ctx  [BA*HID];
__device__ __align__(16) float g_hA   [SL*BA*HID];
__device__ __align__(16) float g_hbt  [TL*BA*HID];   // [t][b][H]
__device__ __align__(16) float g_part [16*4096*16];
// decoder counters use [0,10000); encoder pair-barriers use [10000,10100)
__device__ int g_ctrs[10240];
#define OFF_W0H 0L
#define OFF_W0R 4194304L
#define OFF_WIH 8388608L
#define OFF_WHH 20971520L
#define OFF_WC1 33554432L
#define OFF_WC2 34603008L
__device__ __align__(16) __nv_bfloat16 g_wbf[35651584];
__device__ __align__(16) __nv_bfloat16 g_wout[(long)VOUT*HID];

__device__ __forceinline__ float sigf(float x){ return 1.f/(1.f+expf(-x)); }

__device__ __forceinline__ unsigned cvt_tf32(float f){
    unsigned u;
    asm("cvt.rna.tf32.f32 %0, %1;" : "=r"(u) : "f"(f));
    return u;
}

__global__ void ctrz_k(){ g_ctrs[threadIdx.x + blockIdx.x*256] = 0; }

__global__ void embed_k(const int* __restrict__ idx, const float* __restrict__ W,
                        float* __restrict__ out, int slen){
    int s = blockIdx.x, b = blockIdx.y;
    long tok = idx[b*slen + s];
    const float4* sp = (const float4*)(W + tok*1024);
    float4* dp = (float4*)(out + ((long)s*BA + b)*1024);
    for (int i = threadIdx.x; i < 256; i += blockDim.x) dp[i] = sp[i];
}

__global__ void dinit_k(float* __restrict__ dh, const float* __restrict__ h0,
                        float* __restrict__ dcc, const float* __restrict__ c0,
                        float* __restrict__ htl){
    int i = blockIdx.x*256 + threadIdx.x;
    dh[i] = h0[i];
    dcc[i] = c0[i];
    if (i < BA*HID) htl[i] = 0.f;
}

__global__ void cvtf_k(__nv_bfloat16* __restrict__ dst, const float* __restrict__ src,
                       long total4){
    long stride = (long)gridDim.x*blockDim.x;
    for (long i = (long)blockIdx.x*blockDim.x + threadIdx.x; i < total4; i += stride){
        float4 v = ((const float4*)src)[i];
        ((__nv_bfloat162*)dst)[2*i]   = __floats2bfloat162_rn(v.x, v.y);
        ((__nv_bfloat162*)dst)[2*i+1] = __floats2bfloat162_rn(v.z, v.w);
    }
}
__global__ void cvt_k(__nv_bfloat16* __restrict__ dst, const float* __restrict__ src,
                      int srcld, int col0, int ncols, long total){
    long stride = (long)gridDim.x*blockDim.x;
    for (long i = (long)blockIdx.x*blockDim.x + threadIdx.x; i < total; i += stride){
        long r = i / ncols, cc = i - r*ncols;
        dst[i] = __float2bfloat16(src[r*srcld + col0 + cc]);
    }
}

// ---------- tf32 tensor-core GEMM (fp32 A, fp32 B[N,K]) ----------
__global__ __launch_bounds__(256) void gemm_tc_k(
    const float* __restrict__ A, int lda,
    const float* __restrict__ B, int ldb,
    const float* __restrict__ b1, const float* __restrict__ b2,
    float* __restrict__ C, int ldc, int M, int N, int K)
{
    __shared__ unsigned As[128][36];
    __shared__ unsigned Bs[128][36];
    int tid = threadIdx.x;
    int m0 = blockIdx.y*128, n0 = blockIdx.x*128;
    int warp = tid >> 5, lane = tid & 31;
    int wm = warp >> 2, wn = warp & 3;
    int g = lane >> 2, tg = lane & 3;
    float acc[4][4][4];
#pragma unroll
    for (int mt = 0; mt < 4; mt++)
#pragma unroll
        for (int nt = 0; nt < 4; nt++)
#pragma unroll
            for (int i = 0; i < 4; i++) acc[mt][nt][i] = 0.f;

    for (int k0 = 0; k0 < K; k0 += 32) {
#pragma unroll
        for (int i = 0; i < 4; i++) {
            int e = tid + i*256;
            int m = e >> 3, kq = e & 7;
            float4 v = make_float4(0,0,0,0);
            if (m0 + m < M) v = *(const float4*)(A + (long)(m0+m)*lda + k0 + kq*4);
            unsigned* d = &As[m][kq*4];
            d[0]=cvt_tf32(v.x); d[1]=cvt_tf32(v.y); d[2]=cvt_tf32(v.z); d[3]=cvt_tf32(v.w);
        }
#pragma unroll
        for (int i = 0; i < 4; i++) {
            int e = tid + i*256;
            int n = e >> 3, kq = e & 7;
            float4 v = *(const float4*)(B + (long)(n0+n)*ldb + k0 + kq*4);
            unsigned* d = &Bs[n][kq*4];
            d[0]=cvt_tf32(v.x); d[1]=cvt_tf32(v.y); d[2]=cvt_tf32(v.z); d[3]=cvt_tf32(v.w);
        }
        __syncthreads();
#pragma unroll
        for (int ks = 0; ks < 4; ks++) {
            int kb = ks*8;
            unsigned a[4][4], b[4][2];
#pragma unroll
            for (int mt = 0; mt < 4; mt++) {
                int mb = wm*64 + mt*16;
                a[mt][0] = As[mb+g  ][kb+tg];
                a[mt][1] = As[mb+g+8][kb+tg];
                a[mt][2] = As[mb+g  ][kb+tg+4];
                a[mt][3] = As[mb+g+8][kb+tg+4];
            }
#pragma unroll
            for (int nt = 0; nt < 4; nt++) {
                int nb = wn*32 + nt*8;
                b[nt][0] = Bs[nb+g][kb+tg];
                b[nt][1] = Bs[nb+g][kb+tg+4];
            }
#pragma unroll
            for (int mt = 0; mt < 4; mt++)
#pragma unroll
                for (int nt = 0; nt < 4; nt++)
                    asm volatile(
                        "mma.sync.aligned.m16n8k8.row.col.f32.tf32.tf32.f32 "
                        "{%0,%1,%2,%3}, {%4,%5,%6,%7}, {%8,%9}, {%0,%1,%2,%3};"
                        : "+f"(acc[mt][nt][0]), "+f"(acc[mt][nt][1]),
                          "+f"(acc[mt][nt][2]), "+f"(acc[mt][nt][3])
                        : "r"(a[mt][0]), "r"(a[mt][1]), "r"(a[mt][2]), "r"(a[mt][3]),
                          "r"(b[nt][0]), "r"(b[nt][1]));
        }
        __syncthreads();
    }
#pragma unroll
    for (int mt = 0; mt < 4; mt++) {
#pragma unroll
        for (int h = 0; h < 2; h++) {
            int m = m0 + wm*64 + mt*16 + g + h*8;
            if (m < M) {
#pragma unroll
                for (int nt = 0; nt < 4; nt++) {
                    int n = n0 + wn*32 + nt*8 + tg*2;
                    float v0 = acc[mt][nt][h*2+0];
                    float v1 = acc[mt][nt][h*2+1];
                    if (b1) { v0 += b1[n]; v1 += b1[n+1]; }
                    if (b2) { v0 += b2[n]; v1 += b2[n+1]; }
                    C[(long)m*ldc + n]     = v0;
                    C[(long)m*ldc + n + 1] = v1;
                }
            }
        }
    }
}

// ---------- tf32 GEMM with bf16 B (generator; scattered output rows) --------
__global__ __launch_bounds__(256) void gemm_tcb_k(
    const float* __restrict__ A, int lda,
    const __nv_bfloat16* __restrict__ B, int ldb,
    const float* __restrict__ b1,
    float* __restrict__ C, int ldc, int M, int N, int K, int t0)
{
    __shared__ unsigned As[128][36];
    __shared__ unsigned Bs[128][36];
    int tid = threadIdx.x;
    int m0 = blockIdx.y*128, n0 = blockIdx.x*128;
    int warp = tid >> 5, lane = tid & 31;
    int wm = warp >> 2, wn = warp & 3;
    int g = lane >> 2, tg = lane & 3;
    float acc[4][4][4];
#pragma unroll
    for (int mt = 0; mt < 4; mt++)
#pragma unroll
        for (int nt = 0; nt < 4; nt++)
#pragma unroll
            for (int i = 0; i < 4; i++) acc[mt][nt][i] = 0.f;

    for (int k0 = 0; k0 < K; k0 += 32) {
#pragma unroll
        for (int i = 0; i < 4; i++) {
            int e = tid + i*256;
            int m = e >> 3, kq = e & 7;
            float4 v = make_float4(0,0,0,0);
            if (m0 + m < M) v = *(const float4*)(A + (long)(m0+m)*lda + k0 + kq*4);
            unsigned* d = &As[m][kq*4];
            d[0]=cvt_tf32(v.x); d[1]=cvt_tf32(v.y); d[2]=cvt_tf32(v.z); d[3]=cvt_tf32(v.w);
        }
#pragma unroll
        for (int i = 0; i < 2; i++) {
            int e = tid + i*256;
            int n = e >> 2, ch = e & 3;
            uint4 raw = __ldcs((const uint4*)(B + (long)(n0+n)*ldb + k0 + ch*8));
            const __nv_bfloat162* p = (const __nv_bfloat162*)&raw;
            unsigned* d = &Bs[n][ch*8];
#pragma unroll
            for (int j = 0; j < 4; j++) {
                float2 f = __bfloat1622float2(p[j]);
                d[2*j]   = cvt_tf32(f.x);
                d[2*j+1] = cvt_tf32(f.y);
            }
        }
        __syncthreads();
#pragma unroll
        for (int ks = 0; ks < 4; ks++) {
            int kb = ks*8;
            unsigned a[4][4], b[4][2];
#pragma unroll
            for (int mt = 0; mt < 4; mt++) {
                int mb = wm*64 + mt*16;
                a[mt][0] = As[mb+g  ][kb+tg];
                a[mt][1] = As[mb+g+8][kb+tg];
                a[mt][2] = As[mb+g  ][kb+tg+4];
                a[mt][3] = As[mb+g+8][kb+tg+4];
            }
#pragma unroll
            for (int nt = 0; nt < 4; nt++) {
                int nb = wn*32 + nt*8;
                b[nt][0] = Bs[nb+g][kb+tg];
                b[nt][1] = Bs[nb+g][kb+tg+4];
            }
#pragma unroll
            for (int mt = 0; mt < 4; mt++)
#pragma unroll
                for (int nt = 0; nt < 4; nt++)
                    asm volatile(
                        "mma.sync.aligned.m16n8k8.row.col.f32.tf32.tf32.f32 "
                        "{%0,%1,%2,%3}, {%4,%5,%6,%7}, {%8,%9}, {%0,%1,%2,%3};"
                        : "+f"(acc[mt][nt][0]), "+f"(acc[mt][nt][1]),
                          "+f"(acc[mt][nt][2]), "+f"(acc[mt][nt][3])
                        : "r"(a[mt][0]), "r"(a[mt][1]), "r"(a[mt][2]), "r"(a[mt][3]),
                          "r"(b[nt][0]), "r"(b[nt][1]));
        }
        __syncthreads();
    }
#pragma unroll
    for (int mt = 0; mt < 4; mt++) {
#pragma unroll
        for (int h = 0; h < 2; h++) {
            int m = m0 + wm*64 + mt*16 + g + h*8;
            if (m < M) {
                long crow = (long)(m & 15)*TL + t0 + (m >> 4);
#pragma unroll
                for (int nt = 0; nt < 4; nt++) {
                    int n = n0 + wn*32 + nt*8 + tg*2;
                    C[crow*ldc + n]     = acc[mt][nt][h*2+0] + b1[n];
                    C[crow*ldc + n + 1] = acc[mt][nt][h*2+1] + b1[n+1];
                }
            }
        }
    }
}

// ---------------- scalar fp32 GEMM (small hA GEMM only) ---------------------
__global__ __launch_bounds__(256) void gemm_k(
    const float* __restrict__ A, int lda,
    const float* __restrict__ B, int ldb, int transB,
    float* __restrict__ C, int ldc, int M, int N, int K)
{
    __shared__ float As[16][132];
    __shared__ float Bs[16][132];
    int m0 = blockIdx.y*128, n0 = blockIdx.x*128;
    int tid = threadIdx.x, tx = tid & 15, ty = tid >> 4;
    float acc[8][8];
#pragma unroll
    for (int i = 0; i < 8; i++)
#pragma unroll
        for (int j = 0; j < 8; j++) acc[i][j] = 0.f;

    for (int k0 = 0; k0 < K; k0 += 16) {
#pragma unroll
        for (int i = 0; i < 2; i++) {
            int e = tid + i*256, m = e >> 2, kq = e & 3;
            float4 v = make_float4(0,0,0,0);
            if (m0 + m < M) v = *(const float4*)(A + (long)(m0+m)*lda + k0 + kq*4);
            As[kq*4+0][m]=v.x; As[kq*4+1][m]=v.y; As[kq*4+2][m]=v.z; As[kq*4+3][m]=v.w;
        }
        if (transB) {
#pragma unroll
            for (int i = 0; i < 2; i++) {
                int e = tid + i*256, n = e >> 2, kq = e & 3;
                float4 v = *(const float4*)(B + (long)(n0+n)*ldb + k0 + kq*4);
                Bs[kq*4+0][n]=v.x; Bs[kq*4+1][n]=v.y; Bs[kq*4+2][n]=v.z; Bs[kq*4+3][n]=v.w;
            }
        } else {
#pragma unroll
            for (int i = 0; i < 2; i++) {
                int e = tid + i*256, kk = e >> 5, nq = e & 31;
                *(float4*)&Bs[kk][nq*4] = *(const float4*)(B + (long)(k0+kk)*ldb + n0 + nq*4);
            }
        }
        __syncthreads();
#pragma unroll
        for (int kk = 0; kk < 16; kk++) {
            float a[8], bv[8];
            *(float4*)&a[0] = *(float4*)&As[kk][ty*8];
            *(float4*)&a[4] = *(float4*)&As[kk][ty*8+4];
            *(float4*)&bv[0] = *(float4*)&Bs[kk][tx*8];
            *(float4*)&bv[4] = *(float4*)&Bs[kk][tx*8+4];
#pragma unroll
            for (int i = 0; i < 8; i++)
#pragma unroll
                for (int j = 0; j < 8; j++) acc[i][j] = fmaf(a[i], bv[j], acc[i][j]);
        }
        __syncthreads();
    }
#pragma unroll
    for (int i = 0; i < 8; i++) {
        int m = m0 + ty*8 + i;
        if (m < M) {
            float* Cr = C + (long)m*ldc + n0 + tx*8;
#pragma unroll
            for (int j = 0; j < 8; j++) Cr[j] = acc[i][j];
        }
    }
}

// ------- encoder step body (one step, one block's share; 128-block layout) --
__device__ __forceinline__ void enc_step_dev(
    const float* __restrict__ Whh, const float* __restrict__ xg,
    const float* __restrict__ hin, float* __restrict__ hout,
    float* __restrict__ c, float* __restrict__ y,
    float* __restrict__ h0l, float* __restrict__ c0l, int step,
    float (*hs)[18], float (*sg)[17])
{
    int tid = threadIdx.x;
    int dir = blockIdx.x >> 6, hgrp = blockIdx.x & 63;
    int s = dir ? (SL-1-step) : step;
    int r = tid >> 3, q = tid & 7;
    float a0 = 0.f, a1 = 0.f;

    if (step > 0) {
        const float* hsrc = hin + dir*(BA*HD2);
#pragma unroll
        for (int i = 0; i < 32; i++) {
            int e = tid + i*256;
            hs[e & 511][e >> 9] = __ldcg(hsrc + e);
        }
        __syncthreads();
        int g = r >> 3, j = r & 7;
        const float* wr = Whh + ((long)dir*2048 + g*512 + hgrp*8 + j) * 512;
#pragma unroll 4
        for (int k = 0; k < 512; k += 8) {
            float w8[8];
            *(float4*)&w8[0] = *(const float4*)(wr + k);
            *(float4*)&w8[4] = *(const float4*)(wr + k + 4);
#pragma unroll
            for (int kk = 0; kk < 8; kk++) {
                float2 hv = *(const float2*)&hs[k+kk][2*q];
                a0 = fmaf(w8[kk], hv.x, a0);
                a1 = fmaf(w8[kk], hv.y, a1);
            }
        }
    }
    sg[r][2*q] = a0; sg[r][2*q+1] = a1;
    __syncthreads();

    if (tid < 128) {
        int j = tid >> 4, b = tid & 15;
        int hd = hgrp*8 + j;
        long xb = ((long)s*BA + b)*4096 + dir*2048 + hd;
        float gi = sg[j     ][b] + xg[xb];
        float gf = sg[8  + j][b] + xg[xb + 512];
        float gg = sg[16 + j][b] + xg[xb + 1024];
        float go = sg[24 + j][b] + xg[xb + 1536];
        int ci = dir*(BA*HD2) + b*HD2 + hd;
        float cc = step ? c[ci] : 0.f;
        float cn = sigf(gf)*cc + sigf(gi)*tanhf(gg);
        float hn = sigf(go)*tanhf(cn);
        c[ci] = cn; hout[ci] = hn;
        y[((long)s*BA + b)*HID + dir*512 + hd] = hn;
        if (step == SL-1) {
            h0l[b*HID + dir*512 + hd] = hn;
            c0l[b*HID + dir*512 + hd] = cn;
        }
    }
}

// ------- encoder pair-step: two steps per launch, grid barrier between ------
__global__ __launch_bounds__(256) void enc2_k(
    const float* __restrict__ Whh, const float* __restrict__ xg,
    float* __restrict__ hA, float* __restrict__ hB,
    float* __restrict__ c, float* __restrict__ y,
    float* __restrict__ h0l, float* __restrict__ c0l, int step0, int* ctr)
{
    __shared__ __align__(16) float hs[512][18];
    __shared__ float sg[32][17];
    int tid = threadIdx.x;

    // step A: hA -> hB
    enc_step_dev(Whh, xg, hA, hB, c, y, h0l, c0l, step0, hs, sg);

    // grid barrier (128 blocks, all co-resident)
    __threadfence();
    __syncthreads();
    if (tid == 0) {
        atomicAdd(ctr, 1);
        while (*(volatile int*)ctr < 128) ;
    }
    __syncthreads();

    // step B: hB -> hA
    enc_step_dev(Whh, xg, hB, hA, c, y, h0l, c0l, step0 + 1, hs, sg);
}

// -------- decoder layer: mm + per-rowgroup-ticket cell (+attn) --------------
__global__ __launch_bounds__(256, 4) void mmbf_cell_k(
    const __nv_bfloat16* __restrict__ W1, const __nv_bfloat16* __restrict__ W2,
    const float* __restrict__ x1, const float* __restrict__ x2,
    const float* __restrict__ pre, const float* __restrict__ b1,
    const float* __restrict__ b2,
    float* __restrict__ c, float* __restrict__ hout,
    int* rgc, int* attnc,
    const float* __restrict__ hA, const float* __restrict__ hsrc,
    float* __restrict__ ctx)
{
    __shared__ __align__(16) __nv_bfloat16 Wt[128][136];
    __shared__ __align__(16) float xs[128][20];
    __shared__ int tick;
    int tid = threadIdx.x, bid = blockIdx.x;
    float* part = g_part;
    int slice = bid & 15, rg = bid >> 4;

    {
        int r0 = rg*128, k0 = slice*128;
        const __nv_bfloat16* W; const float* x; int ko;
        if (k0 < 1024) { W = W1; x = x1; ko = k0; }
        else           { W = W2; x = x2; ko = k0 - 1024; }
        uint4 wc[8];
        float xr[8];
#pragma unroll
        for (int i = 0; i < 8; i++) {
            int cidx = tid + i*256;
            int row = cidx >> 4, qq = cidx & 15;
            wc[i] = *(const uint4*)(W + (long)(r0+row)*1024 + ko + qq*8);
        }
#pragma unroll
        for (int i = 0; i < 8; i++) {
            int e = tid + i*256;
            int b = e >> 7, kk = e & 127;
            xr[i] = __ldcg(x + b*1024 + ko + kk);
        }
#pragma unroll
        for (int i = 0; i < 8; i++) {
            int cidx = tid + i*256;
            int row = cidx >> 4, qq = cidx & 15;
            *(uint4*)&Wt[row][qq*8] = wc[i];
        }
#pragma unroll
        for (int i = 0; i < 8; i++) {
            int e = tid + i*256;
            int b = e >> 7, kk = e & 127;
            xs[kk][b] = xr[i];
        }
        __syncthreads();
        int rp = tid >> 2, bq = tid & 3;
        float a00=0,a01=0,a02=0,a03=0,a10=0,a11=0,a12=0,a13=0;
#pragma unroll 8
        for (int k = 0; k < 128; k += 2) {
            __nv_bfloat162 wa = *(const __nv_bfloat162*)&Wt[2*rp  ][k];
            __nv_bfloat162 wb = *(const __nv_bfloat162*)&Wt[2*rp+1][k];
            float2 fa = __bfloat1622float2(wa);
            float2 fb = __bfloat1622float2(wb);
            float4 x0 = *(const float4*)&xs[k  ][4*bq];
            float4 x1v = *(const float4*)&xs[k+1][4*bq];
            a00 = fmaf(fa.x, x0.x, a00); a01 = fmaf(fa.x, x0.y, a01);
            a02 = fmaf(fa.x, x0.z, a02); a03 = fmaf(fa.x, x0.w, a03);
            a10 = fmaf(fb.x, x0.x, a10); a11 = fmaf(fb.x, x0.y, a11);
            a12 = fmaf(fb.x, x0.z, a12); a13 = fmaf(fb.x, x0.w, a13);
            a00 = fmaf(fa.y, x1v.x, a00); a01 = fmaf(fa.y, x1v.y, a01);
            a02 = fmaf(fa.y, x1v.z, a02); a03 = fmaf(fa.y, x1v.w, a03);
            a10 = fmaf(fb.y, x1v.x, a10); a11 = fmaf(fb.y, x1v.y, a11);
            a12 = fmaf(fb.y, x1v.z, a12); a13 = fmaf(fb.y, x1v.w, a13);
        }
        float* p = part + ((long)slice*4096 + r0 + 2*rp)*16 + 4*bq;
        *(float4*)p        = make_float4(a00,a01,a02,a03);
        *(float4*)(p + 16) = make_float4(a10,a11,a12,a13);
    }
    __threadfence();
    __syncthreads();
    if (tid == 0) atomicAdd(&rgc[rg], 1);

    if (slice < 14) return;
    int cb = (slice - 14)*32 + rg;
    if (tid < 4) {
        int need = 8*tid + (cb >> 3);
        while (*(volatile int*)&rgc[need] < 16) ;
    }
    __syncthreads();
    {
        int idx = cb*256 + tid;
        int b = idx & 15, hd = idx >> 4;
        float g[4];
#pragma unroll
        for (int gi = 0; gi < 4; gi++) {
            int row = gi*HID + hd;
            float v;
            if (pre) v = pre[(long)b*4096 + row];
            else     v = b1[row] + b2[row];
#pragma unroll
            for (int sl = 0; sl < 16; sl++)
                v += __ldcg(part + ((long)sl*4096 + row)*16 + b);
            g[gi] = v;
        }
        int ci = b*HID + hd;
        float cc = c[ci];
        float cn = sigf(g[1])*cc + sigf(g[0])*tanhf(g[2]);
        c[ci] = cn;
        hout[ci] = sigf(g[3])*tanhf(cn);
    }
    if (!attnc) return;

    __threadfence();
    __syncthreads();
    if (tid == 0) tick = atomicAdd(attnc, 1);
    __syncthreads();
    int t2 = tick;
    if (t2 < 48) return;
    if (tid == 0) { while (*(volatile int*)attnc < 64) ; }
    __syncthreads();
    {
        int b = t2 - 48;
        float* h3s = (float*)&Wt[0][0];
        float* sc  = h3s + 1024;
        for (int i = tid; i < HID; i += 256) h3s[i] = __ldcg(hout + b*HID + i);
        __syncthreads();
        int w = tid >> 5, lane = tid & 31;
        for (int s = w; s < SL; s += 8) {
            const float* hp = hA + ((long)s*BA + b)*HID;
            float p = 0.f;
            for (int k = lane; k < HID; k += 32) p = fmaf(h3s[k], hp[k], p);
#pragma unroll
            for (int o = 16; o > 0; o >>= 1) p += __shfl_xor_sync(0xffffffffu, p, o);
            if (lane == 0) sc[s] = p;
        }
        __syncthreads();
        if (tid == 0) {
            float mx = sc[0];
            for (int s = 1; s < SL; s++) mx = fmaxf(mx, sc[s]);
            float sum = 0.f;
            for (int s = 0; s < SL; s++) { sc[s] = expf(sc[s]-mx); sum += sc[s]; }
            float inv = 1.f/sum;
            for (int s = 0; s < SL; s++) sc[s] *= inv;
        }
        __syncthreads();
        float4 acc = make_float4(0,0,0,0);
        int k = tid*4;
        for (int s = 0; s < SL; s++) {
            float ws = sc[s];
            float4 v = *(const float4*)(hsrc + ((long)s*BA + b)*HID + k);
            acc.x = fmaf(ws, v.x, acc.x); acc.y = fmaf(ws, v.y, acc.y);
            acc.z = fmaf(ws, v.z, acc.z); acc.w = fmaf(ws, v.w, acc.w);
        }
        *(float4*)(ctx + b*HID + k) = acc;
    }
}

// -------- h_tilde: mm (128 blocks) + rowgroup-ticket tanh --------
__global__ __launch_bounds__(256, 4) void mmbf_ht_k(
    const __nv_bfloat16* __restrict__ W1, const __nv_bfloat16* __restrict__ W2,
    const float* __restrict__ x1, const float* __restrict__ x2,
    const float* __restrict__ bc,
    float* __restrict__ htl, float* __restrict__ hbt, int t, int* rgc)
{
    __shared__ __align__(16) __nv_bfloat16 Wt[128][136];
    __shared__ __align__(16) float xs[128][20];
    int tid = threadIdx.x, bid = blockIdx.x;
    float* part = g_part;
    int slice = bid & 15, rg = bid >> 4;
    {
        int r0 = rg*128, k0 = slice*128;
        const __nv_bfloat16* W; const float* x; int ko;
        if (k0 < 1024) { W = W1; x = x1; ko = k0; }
        else           { W = W2; x = x2; ko = k0 - 1024; }
        uint4 wc[8];
        float xr[8];
#pragma unroll
        for (int i = 0; i < 8; i++) {
            int cidx = tid + i*256;
            int row = cidx >> 4, qq = cidx & 15;
            wc[i] = *(const uint4*)(W + (long)(r0+row)*1024 + ko + qq*8);
        }
#pragma unroll
        for (int i = 0; i < 8; i++) {
            int e = tid + i*256;
            int b = e >> 7, kk = e & 127;
            xr[i] = __ldcg(x + b*1024 + ko + kk);
        }
#pragma unroll
        for (int i = 0; i < 8; i++) {
            int cidx = tid + i*256;
            int row = cidx >> 4, qq = cidx & 15;
            *(uint4*)&Wt[row][qq*8] = wc[i];
        }
#pragma unroll
        for (int i = 0; i < 8; i++) {
            int e = tid + i*256;
            int b = e >> 7, kk = e & 127;
            xs[kk][b] = xr[i];
        }
        __syncthreads();
        int rp = tid >> 2, bq = tid & 3;
        float a00=0,a01=0,a02=0,a03=0,a10=0,a11=0,a12=0,a13=0;
#pragma unroll 8
        for (int k = 0; k < 128; k += 2) {
            __nv_bfloat162 wa = *(const __nv_bfloat162*)&Wt[2*rp  ][k];
            __nv_bfloat162 wb = *(const __nv_bfloat162*)&Wt[2*rp+1][k];
            float2 fa = __bfloat1622float2(wa);
            float2 fb = __bfloat1622float2(wb);
            float4 x0 = *(const float4*)&xs[k  ][4*bq];
            float4 x1v = *(const float4*)&xs[k+1][4*bq];
            a00 = fmaf(fa.x, x0.x, a00); a01 = fmaf(fa.x, x0.y, a01);
            a02 = fmaf(fa.x, x0.z, a02); a03 = fmaf(fa.x, x0.w, a03);
            a10 = fmaf(fb.x, x0.x, a10); a11 = fmaf(fb.x, x0.y, a11);
            a12 = fmaf(fb.x, x0.z, a12); a13 = fmaf(fb.x, x0.w, a13);
            a00 = fmaf(fa.y, x1v.x, a00); a01 = fmaf(fa.y, x1v.y, a01);
            a02 = fmaf(fa.y, x1v.z, a02); a03 = fmaf(fa.y, x1v.w, a03);
            a10 = fmaf(fb.y, x1v.x, a10); a11 = fmaf(fb.y, x1v.y, a11);
            a12 = fmaf(fb.y, x1v.z, a12); a13 = fmaf(fb.y, x1v.w, a13);
        }
        float* p = part + ((long)slice*1024 + r0 + 2*rp)*16 + 4*bq;
        *(float4*)p        = make_float4(a00,a01,a02,a03);
        *(float4*)(p + 16) = make_float4(a10,a11,a12,a13);
    }
    __threadfence();
    __syncthreads();
    if (tid == 0) atomicAdd(&rgc[rg], 1);

    if (slice < 8) return;
    int cb = (slice - 8)*8 + rg;
    if (tid == 0) { while (*(volatile int*)&rgc[cb >> 3] < 16) ; }
    __syncthreads();
    {
        int idx = cb*256 + tid;
        int b = idx & 15, hd = idx >> 4;
        float v = bc[hd];
#pragma unroll
        for (int sl = 0; sl < 16; sl++)
            v += __ldcg(part + ((long)sl*1024 + hd)*16 + b);
        float h = tanhf(v);
        htl[b*HID + hd] = h;
        hbt[((long)t*BA + b)*HID + hd] = h;
    }
}

// ---------------- log-softmax ----------------
__global__ __launch_bounds__(256) void lsm_k(float* __restrict__ out)
{
    __shared__ float red[256];
    long m = blockIdx.x;
    float* row = out + m*VOUT;
    int tid = threadIdx.x;
    float mx = -1e30f;
    for (int i = tid; i < VOUT/4; i += 256) {
        float4 v = *(const float4*)(row + i*4);
        mx = fmaxf(mx, fmaxf(fmaxf(v.x, v.y), fmaxf(v.z, v.w)));
    }
    red[tid] = mx; __syncthreads();
    for (int o = 128; o > 0; o >>= 1) { if (tid < o) red[tid] = fmaxf(red[tid], red[tid+o]); __syncthreads(); }
    mx = red[0]; __syncthreads();
    float sum = 0.f;
    for (int i = tid; i < VOUT/4; i += 256) {
        float4 v = *(const float4*)(row + i*4);
        sum += expf(v.x-mx)+expf(v.y-mx)+expf(v.z-mx)+expf(v.w-mx);
    }
    red[tid] = sum; __syncthreads();
    for (int o = 128; o > 0; o >>= 1) { if (tid < o) red[tid] += red[tid+o]; __syncthreads(); }
    float lse = mx + logf(red[0]);
    for (int i = tid; i < VOUT/4; i += 256) {
        float4 v = *(const float4*)(row + i*4);
        v.x -= lse; v.y -= lse; v.z -= lse; v.w -= lse;
        *(float4*)(row + i*4) = v;
    }
}

static float* sym(const void* s){ void* p = nullptr; cudaGetSymbolAddress(&p, s); return (float*)p; }

extern "C" void kernel_launch(void* const* d_in, const int* in_sizes, int n_in,
                              void* d_out, int out_size)
{
    const int*   src   = (const int*)  d_in[0];
    const int*   tgt   = (const int*)  d_in[1];
    const float* embS  = (const float*)d_in[2];
    const float* embD  = (const float*)d_in[3];
    const float* eWih  = (const float*)d_in[4];
    const float* eWhh  = (const float*)d_in[5];
    const float* ebih  = (const float*)d_in[6];
    const float* ebhh  = (const float*)d_in[7];
    const float* d0Wih = (const float*)d_in[8];
    const float* d0Whh = (const float*)d_in[9];
    const float* d0bih = (const float*)d_in[10];
    const float* d0bhh = (const float*)d_in[11];
    const float* dWih  = (const float*)d_in[12];
    const float* dWhh  = (const float*)d_in[13];
    const float* dbih  = (const float*)d_in[14];
    const float* dbhh  = (const float*)d_in[15];
    const float* Wattn = (const float*)d_in[16];
    const float* Wcat  = (const float*)d_in[17];
    const float* bcat  = (const float*)d_in[18];
    const float* Wout  = (const float*)d_in[19];
    const float* bout  = (const float*)d_in[20];
    float* out = (float*)d_out;

    float* encx = sym(g_encx);  float* ency = sym(g_ency);
    float* encxg = sym(g_encxg);
    float* ehA = sym(g_enchA);  float* ehB = sym(g_enchB);
    float* ecc = sym(g_encc);
    float* h0 = sym(g_h0);      float* c0 = sym(g_c0);
    float* demb = sym(g_demb);  float* pre0 = sym(g_pre0);
    float* dhA = sym(g_dhA);    float* dhB = sym(g_dhB);
    float* dc  = sym(g_dc);
    float* htl = sym(g_htl);    float* ctx = sym(g_ctx);
    float* hAp = sym(g_hA);     float* hbt = sym(g_hbt);
    __nv_bfloat16* wbf = (__nv_bfloat16*)sym(g_wbf);
    __nv_bfloat16* wout = (__nv_bfloat16*)sym(g_wout);
    int* ctrs = (int*)sym(g_ctrs);

    static cudaStream_t s2 = nullptr;
    static cudaEvent_t evf, evpre;
    if (!s2) {
        cudaStreamCreateWithFlags(&s2, cudaStreamNonBlocking);
        cudaEventCreateWithFlags(&evf, cudaEventDisableTiming);
        cudaEventCreateWithFlags(&evpre, cudaEventDisableTiming);
    }

    ctrz_k<<<40, 256>>>();
    cudaEventRecord(evf, 0);
    cudaStreamWaitEvent(s2, evf, 0);

    // ---- precompute on s2 (overlaps encoder on s0) ----
    {
        long n1 = 4194304L, n3 = 12582912L, nc = 1048576L;
        cvt_k <<<1024, 256, 0, s2>>>(wbf + OFF_W0H, d0Wih, 2048, 1024, 1024, n1);
        cvtf_k<<<1024, 256, 0, s2>>>(wbf + OFF_W0R, d0Whh, n1/4);
        cvtf_k<<<2048, 256, 0, s2>>>(wbf + OFF_WIH, dWih, n3/4);
        cvtf_k<<<2048, 256, 0, s2>>>(wbf + OFF_WHH, dWhh, n3/4);
        cvt_k <<<512, 256, 0, s2>>>(wbf + OFF_WC1, Wcat, 2048, 0, 1024, nc);
        cvt_k <<<512, 256, 0, s2>>>(wbf + OFF_WC2, Wcat, 2048, 1024, 1024, nc);
        cvtf_k<<<2048, 256, 0, s2>>>(wout, Wout, (long)VOUT*HID/4);
        embed_k<<<dim3(TL, BA), 256, 0, s2>>>(tgt, embD, demb, TL);
        gemm_tc_k<<<dim3(32, 7), 256, 0, s2>>>(demb, HID, d0Wih, 2048, d0bih, d0bhh,
                                               pre0, 4096, TL*BA, 4096, 1024);
    }
    cudaEventRecord(evpre, s2);

    // ---- encoder on s0 (pair-stepped: 25 launches per layer) ----
    embed_k<<<dim3(SL, BA), 256>>>(src, embS, encx, SL);
    float* xin = encx; float* yout = ency;
    for (int l = 0; l < NL; l++) {
        gemm_tc_k<<<dim3(32, 7), 256>>>(xin, HID, eWih + (long)l*4096*1024, 1024,
                                        ebih + l*4096, ebhh + l*4096, encxg, 4096,
                                        SL*BA, 4096, 1024);
        const float* Whh = eWhh + (long)l*4096*512;
        for (int st = 0; st < SL; st += 2) {
            enc2_k<<<128, 256>>>(Whh, encxg, ehA, ehB, ecc, yout,
                                 h0 + (long)l*BA*HID, c0 + (long)l*BA*HID,
                                 st, ctrs + 10000 + l*25 + (st >> 1));
        }
        float* t = xin; xin = yout; yout = t;
    }
    float* hsrc = xin;

    gemm_k<<<dim3(8, 7), 256>>>(hsrc, HID, Wattn, 1024, 0, hAp, HID,
                                SL*BA, 1024, 1024);
    dinit_k<<<NL*BA*HID/256, 256>>>(dhA, h0, dc, c0, htl);
    cudaStreamWaitEvent(0, evpre, 0);

    // ---- decoder loop: 5 kernels/step ----
    for (int t = 0; t < TL; t++) {
        float* hprev = (t & 1) ? dhB : dhA;
        float* hcur  = (t & 1) ? dhA : dhB;
        int base = t*5*40;
        mmbf_cell_k<<<512, 256>>>(wbf + OFF_W0H, wbf + OFF_W0R, htl, hprev,
                                  pre0 + (long)t*BA*4096, nullptr, nullptr,
                                  dc, hcur,
                                  ctrs + base, nullptr, nullptr, nullptr, nullptr);
        for (int i = 0; i < NL-1; i++) {
            int last = (i == NL-2);
            int b2 = base + (i+1)*40;
            mmbf_cell_k<<<512, 256>>>(wbf + OFF_WIH + (long)i*4194304,
                                      wbf + OFF_WHH + (long)i*4194304,
                                      hcur + (long)i*BA*HID,
                                      hprev + (long)(i+1)*BA*HID,
                                      nullptr, dbih + i*4096, dbhh + i*4096,
                                      dc + (long)(i+1)*BA*HID,
                                      hcur + (long)(i+1)*BA*HID,
                                      ctrs + b2,
                                      last ? (ctrs + b2 + 32) : nullptr,
                                      last ? hAp : nullptr,
                                      last ? hsrc : nullptr,
                                      last ? ctx : nullptr);
        }
        mmbf_ht_k<<<128, 256>>>(wbf + OFF_WC1, wbf + OFF_WC2,
                                hcur + (long)3*BA*HID, ctx,
                                bcat, htl, hbt, t, ctrs + base + 4*40);
    }

    // ---- generator (serial, bf16 weights) ----
    gemm_tcb_k<<<dim3(250, 7), 256>>>(hbt, HID, wout, 1024, bout,
                                      out, VOUT, TL*BA, VOUT, HID, 0);
    lsm_k<<<TL*BA, 256>>>(out);
}

// round 16
// speedup vs baseline: 1.2710x; 1.2710x over previous
#include <cuda_runtime.h>
#include <cuda_bf16.h>
#include <math.h>

#define SL 50
#define TL 50
#define BA 16
#define HID 1024
#define HD2 512
#define NL 4
#define VOUT 32000

__device__ __align__(16) float g_encx [SL*BA*HID];
__device__ __align__(16) float g_ency [SL*BA*HID];
__device__ __align__(16) float g_encxg[SL*BA*4096];
__device__ __align__(16) float g_enchA[2*BA*HD2];
__device__ __align__(16) float g_enchB[2*BA*HD2];
__device__ __align__(16) float g_encc [2*BA*HD2];
__device__ __align__(16) float g_h0   [NL*BA*HID];
__device__ __align__(16) float g_c0   [NL*BA*HID];
__device__ __align__(16) float g_demb [TL*BA*HID];
__device__ __align__(16) float g_pre0 [TL*BA*4096];
__device__ __align__(16) float g_dhA  [NL*BA*HID];
__device__ __align__(16) float g_dhB  [NL*BA*HID];
__device__ __align__(16) float g_dc   [NL*BA*HID];
__device__ __align__(16) float g_htl  [BA*HID];
__device__ __align__(16) float g_ctx  [BA*HID];
__device__ __align__(16) float g_hA   [SL*BA*HID];
__device__ __align__(16) float g_hbt  [TL*BA*HID];   // [t][b][H]
__device__ __align__(16) float g_part [16*4096*16];
__device__ int g_ctrs[10240];   // per-call: 32 rowgroup ctrs + 1 attn ctr (stride 40)
#define OFF_W0H 0L
#define OFF_W0R 4194304L
#define OFF_WIH 8388608L
#define OFF_WHH 20971520L
#define OFF_WC1 33554432L
#define OFF_WC2 34603008L
__device__ __align__(16) __nv_bfloat16 g_wbf[35651584];
__device__ __align__(16) __nv_bfloat16 g_wout[(long)VOUT*HID];

__device__ __forceinline__ float sigf(float x){ return 1.f/(1.f+expf(-x)); }

__device__ __forceinline__ unsigned cvt_tf32(float f){
    unsigned u;
    asm("cvt.rna.tf32.f32 %0, %1;" : "=r"(u) : "f"(f));
    return u;
}

__global__ void ctrz_k(){ g_ctrs[threadIdx.x + blockIdx.x*256] = 0; }

__global__ void embed_k(const int* __restrict__ idx, const float* __restrict__ W,
                        float* __restrict__ out, int slen){
    int s = blockIdx.x, b = blockIdx.y;
    long tok = idx[b*slen + s];
    const float4* sp = (const float4*)(W + tok*1024);
    float4* dp = (float4*)(out + ((long)s*BA + b)*1024);
    for (int i = threadIdx.x; i < 256; i += blockDim.x) dp[i] = sp[i];
}

__global__ void dinit_k(float* __restrict__ dh, const float* __restrict__ h0,
                        float* __restrict__ dcc, const float* __restrict__ c0,
                        float* __restrict__ htl){
    int i = blockIdx.x*256 + threadIdx.x;
    dh[i] = h0[i];
    dcc[i] = c0[i];
    if (i < BA*HID) htl[i] = 0.f;
}

__global__ void cvtf_k(__nv_bfloat16* __restrict__ dst, const float* __restrict__ src,
                       long total4){
    long stride = (long)gridDim.x*blockDim.x;
    for (long i = (long)blockIdx.x*blockDim.x + threadIdx.x; i < total4; i += stride){
        float4 v = ((const float4*)src)[i];
        ((__nv_bfloat162*)dst)[2*i]   = __floats2bfloat162_rn(v.x, v.y);
        ((__nv_bfloat162*)dst)[2*i+1] = __floats2bfloat162_rn(v.z, v.w);
    }
}
__global__ void cvt_k(__nv_bfloat16* __restrict__ dst, const float* __restrict__ src,
                      int srcld, int col0, int ncols, long total){
    long stride = (long)gridDim.x*blockDim.x;
    for (long i = (long)blockIdx.x*blockDim.x + threadIdx.x; i < total; i += stride){
        long r = i / ncols, cc = i - r*ncols;
        dst[i] = __float2bfloat16(src[r*srcld + col0 + cc]);
    }
}

// ---------- tf32 tensor-core GEMM (fp32 A, fp32 B[N,K]) ----------
__global__ __launch_bounds__(256) void gemm_tc_k(
    const float* __restrict__ A, int lda,
    const float* __restrict__ B, int ldb,
    const float* __restrict__ b1, const float* __restrict__ b2,
    float* __restrict__ C, int ldc, int M, int N, int K)
{
    __shared__ unsigned As[128][36];
    __shared__ unsigned Bs[128][36];
    int tid = threadIdx.x;
    int m0 = blockIdx.y*128, n0 = blockIdx.x*128;
    int warp = tid >> 5, lane = tid & 31;
    int wm = warp >> 2, wn = warp & 3;
    int g = lane >> 2, tg = lane & 3;
    float acc[4][4][4];
#pragma unroll
    for (int mt = 0; mt < 4; mt++)
#pragma unroll
        for (int nt = 0; nt < 4; nt++)
#pragma unroll
            for (int i = 0; i < 4; i++) acc[mt][nt][i] = 0.f;

    for (int k0 = 0; k0 < K; k0 += 32) {
#pragma unroll
        for (int i = 0; i < 4; i++) {
            int e = tid + i*256;
            int m = e >> 3, kq = e & 7;
            float4 v = make_float4(0,0,0,0);
            if (m0 + m < M) v = *(const float4*)(A + (long)(m0+m)*lda + k0 + kq*4);
            unsigned* d = &As[m][kq*4];
            d[0]=cvt_tf32(v.x); d[1]=cvt_tf32(v.y); d[2]=cvt_tf32(v.z); d[3]=cvt_tf32(v.w);
        }
#pragma unroll
        for (int i = 0; i < 4; i++) {
            int e = tid + i*256;
            int n = e >> 3, kq = e & 7;
            float4 v = *(const float4*)(B + (long)(n0+n)*ldb + k0 + kq*4);
            unsigned* d = &Bs[n][kq*4];
            d[0]=cvt_tf32(v.x); d[1]=cvt_tf32(v.y); d[2]=cvt_tf32(v.z); d[3]=cvt_tf32(v.w);
        }
        __syncthreads();
#pragma unroll
        for (int ks = 0; ks < 4; ks++) {
            int kb = ks*8;
            unsigned a[4][4], b[4][2];
#pragma unroll
            for (int mt = 0; mt < 4; mt++) {
                int mb = wm*64 + mt*16;
                a[mt][0] = As[mb+g  ][kb+tg];
                a[mt][1] = As[mb+g+8][kb+tg];
                a[mt][2] = As[mb+g  ][kb+tg+4];
                a[mt][3] = As[mb+g+8][kb+tg+4];
            }
#pragma unroll
            for (int nt = 0; nt < 4; nt++) {
                int nb = wn*32 + nt*8;
                b[nt][0] = Bs[nb+g][kb+tg];
                b[nt][1] = Bs[nb+g][kb+tg+4];
            }
#pragma unroll
            for (int mt = 0; mt < 4; mt++)
#pragma unroll
                for (int nt = 0; nt < 4; nt++)
                    asm volatile(
                        "mma.sync.aligned.m16n8k8.row.col.f32.tf32.tf32.f32 "
                        "{%0,%1,%2,%3}, {%4,%5,%6,%7}, {%8,%9}, {%0,%1,%2,%3};"
                        : "+f"(acc[mt][nt][0]), "+f"(acc[mt][nt][1]),
                          "+f"(acc[mt][nt][2]), "+f"(acc[mt][nt][3])
                        : "r"(a[mt][0]), "r"(a[mt][1]), "r"(a[mt][2]), "r"(a[mt][3]),
                          "r"(b[nt][0]), "r"(b[nt][1]));
        }
        __syncthreads();
    }
#pragma unroll
    for (int mt = 0; mt < 4; mt++) {
#pragma unroll
        for (int h = 0; h < 2; h++) {
            int m = m0 + wm*64 + mt*16 + g + h*8;
            if (m < M) {
#pragma unroll
                for (int nt = 0; nt < 4; nt++) {
                    int n = n0 + wn*32 + nt*8 + tg*2;
                    float v0 = acc[mt][nt][h*2+0];
                    float v1 = acc[mt][nt][h*2+1];
                    if (b1) { v0 += b1[n]; v1 += b1[n+1]; }
                    if (b2) { v0 += b2[n]; v1 += b2[n+1]; }
                    C[(long)m*ldc + n]     = v0;
                    C[(long)m*ldc + n + 1] = v1;
                }
            }
        }
    }
}

// ---------- tf32 GEMM with bf16 B (generator; scattered output rows) --------
__global__ __launch_bounds__(256) void gemm_tcb_k(
    const float* __restrict__ A, int lda,
    const __nv_bfloat16* __restrict__ B, int ldb,
    const float* __restrict__ b1,
    float* __restrict__ C, int ldc, int M, int N, int K, int t0)
{
    __shared__ unsigned As[128][36];
    __shared__ unsigned Bs[128][36];
    int tid = threadIdx.x;
    int m0 = blockIdx.y*128, n0 = blockIdx.x*128;
    int warp = tid >> 5, lane = tid & 31;
    int wm = warp >> 2, wn = warp & 3;
    int g = lane >> 2, tg = lane & 3;
    float acc[4][4][4];
#pragma unroll
    for (int mt = 0; mt < 4; mt++)
#pragma unroll
        for (int nt = 0; nt < 4; nt++)
#pragma unroll
            for (int i = 0; i < 4; i++) acc[mt][nt][i] = 0.f;

    for (int k0 = 0; k0 < K; k0 += 32) {
#pragma unroll
        for (int i = 0; i < 4; i++) {
            int e = tid + i*256;
            int m = e >> 3, kq = e & 7;
            float4 v = make_float4(0,0,0,0);
            if (m0 + m < M) v = *(const float4*)(A + (long)(m0+m)*lda + k0 + kq*4);
            unsigned* d = &As[m][kq*4];
            d[0]=cvt_tf32(v.x); d[1]=cvt_tf32(v.y); d[2]=cvt_tf32(v.z); d[3]=cvt_tf32(v.w);
        }
#pragma unroll
        for (int i = 0; i < 2; i++) {
            int e = tid + i*256;
            int n = e >> 2, ch = e & 3;
            uint4 raw = __ldcs((const uint4*)(B + (long)(n0+n)*ldb + k0 + ch*8));
            const __nv_bfloat162* p = (const __nv_bfloat162*)&raw;
            unsigned* d = &Bs[n][ch*8];
#pragma unroll
            for (int j = 0; j < 4; j++) {
                float2 f = __bfloat1622float2(p[j]);
                d[2*j]   = cvt_tf32(f.x);
                d[2*j+1] = cvt_tf32(f.y);
            }
        }
        __syncthreads();
#pragma unroll
        for (int ks = 0; ks < 4; ks++) {
            int kb = ks*8;
            unsigned a[4][4], b[4][2];
#pragma unroll
            for (int mt = 0; mt < 4; mt++) {
                int mb = wm*64 + mt*16;
                a[mt][0] = As[mb+g  ][kb+tg];
                a[mt][1] = As[mb+g+8][kb+tg];
                a[mt][2] = As[mb+g  ][kb+tg+4];
                a[mt][3] = As[mb+g+8][kb+tg+4];
            }
#pragma unroll
            for (int nt = 0; nt < 4; nt++) {
                int nb = wn*32 + nt*8;
                b[nt][0] = Bs[nb+g][kb+tg];
                b[nt][1] = Bs[nb+g][kb+tg+4];
            }
#pragma unroll
            for (int mt = 0; mt < 4; mt++)
#pragma unroll
                for (int nt = 0; nt < 4; nt++)
                    asm volatile(
                        "mma.sync.aligned.m16n8k8.row.col.f32.tf32.tf32.f32 "
                        "{%0,%1,%2,%3}, {%4,%5,%6,%7}, {%8,%9}, {%0,%1,%2,%3};"
                        : "+f"(acc[mt][nt][0]), "+f"(acc[mt][nt][1]),
                          "+f"(acc[mt][nt][2]), "+f"(acc[mt][nt][3])
                        : "r"(a[mt][0]), "r"(a[mt][1]), "r"(a[mt][2]), "r"(a[mt][3]),
                          "r"(b[nt][0]), "r"(b[nt][1]));
        }
        __syncthreads();
    }
#pragma unroll
    for (int mt = 0; mt < 4; mt++) {
#pragma unroll
        for (int h = 0; h < 2; h++) {
            int m = m0 + wm*64 + mt*16 + g + h*8;
            if (m < M) {
                long crow = (long)(m & 15)*TL + t0 + (m >> 4);
#pragma unroll
                for (int nt = 0; nt < 4; nt++) {
                    int n = n0 + wn*32 + nt*8 + tg*2;
                    C[crow*ldc + n]     = acc[mt][nt][h*2+0] + b1[n];
                    C[crow*ldc + n + 1] = acc[mt][nt][h*2+1] + b1[n+1];
                }
            }
        }
    }
}

// ---------------- scalar fp32 GEMM (small hA GEMM only) ---------------------
__global__ __launch_bounds__(256) void gemm_k(
    const float* __restrict__ A, int lda,
    const float* __restrict__ B, int ldb, int transB,
    float* __restrict__ C, int ldc, int M, int N, int K)
{
    __shared__ float As[16][132];
    __shared__ float Bs[16][132];
    int m0 = blockIdx.y*128, n0 = blockIdx.x*128;
    int tid = threadIdx.x, tx = tid & 15, ty = tid >> 4;
    float acc[8][8];
#pragma unroll
    for (int i = 0; i < 8; i++)
#pragma unroll
        for (int j = 0; j < 8; j++) acc[i][j] = 0.f;

    for (int k0 = 0; k0 < K; k0 += 16) {
#pragma unroll
        for (int i = 0; i < 2; i++) {
            int e = tid + i*256, m = e >> 2, kq = e & 3;
            float4 v = make_float4(0,0,0,0);
            if (m0 + m < M) v = *(const float4*)(A + (long)(m0+m)*lda + k0 + kq*4);
            As[kq*4+0][m]=v.x; As[kq*4+1][m]=v.y; As[kq*4+2][m]=v.z; As[kq*4+3][m]=v.w;
        }
        if (transB) {
#pragma unroll
            for (int i = 0; i < 2; i++) {
                int e = tid + i*256, n = e >> 2, kq = e & 3;
                float4 v = *(const float4*)(B + (long)(n0+n)*ldb + k0 + kq*4);
                Bs[kq*4+0][n]=v.x; Bs[kq*4+1][n]=v.y; Bs[kq*4+2][n]=v.z; Bs[kq*4+3][n]=v.w;
            }
        } else {
#pragma unroll
            for (int i = 0; i < 2; i++) {
                int e = tid + i*256, kk = e >> 5, nq = e & 31;
                *(float4*)&Bs[kk][nq*4] = *(const float4*)(B + (long)(k0+kk)*ldb + n0 + nq*4);
            }
        }
        __syncthreads();
#pragma unroll
        for (int kk = 0; kk < 16; kk++) {
            float a[8], bv[8];
            *(float4*)&a[0] = *(float4*)&As[kk][ty*8];
            *(float4*)&a[4] = *(float4*)&As[kk][ty*8+4];
            *(float4*)&bv[0] = *(float4*)&Bs[kk][tx*8];
            *(float4*)&bv[4] = *(float4*)&Bs[kk][tx*8+4];
#pragma unroll
            for (int i = 0; i < 8; i++)
#pragma unroll
                for (int j = 0; j < 8; j++) acc[i][j] = fmaf(a[i], bv[j], acc[i][j]);
        }
        __syncthreads();
    }
#pragma unroll
    for (int i = 0; i < 8; i++) {
        int m = m0 + ty*8 + i;
        if (m < M) {
            float* Cr = C + (long)m*ldc + n0 + tx*8;
#pragma unroll
            for (int j = 0; j < 8; j++) Cr[j] = acc[i][j];
        }
    }
}

// ------- fused encoder step: 128 blocks, both dirs ----
__global__ __launch_bounds__(256) void enc_fused_k(
    const float* __restrict__ Whh, const float* __restrict__ xg,
    const float* __restrict__ hin, float* __restrict__ hout,
    float* __restrict__ c, float* __restrict__ y,
    float* __restrict__ h0l, float* __restrict__ c0l, int step)
{
    __shared__ __align__(16) float hs[512][18];
    __shared__ float sg[32][17];
    int tid = threadIdx.x;
    int dir = blockIdx.x >> 6, hgrp = blockIdx.x & 63;
    int s = dir ? (SL-1-step) : step;
    int r = tid >> 3, q = tid & 7;
    float a0 = 0.f, a1 = 0.f;

    if (step > 0) {
        const float* hsrc = hin + dir*(BA*HD2);
#pragma unroll
        for (int i = 0; i < 32; i++) {
            int e = tid + i*256;
            hs[e & 511][e >> 9] = hsrc[e];
        }
        __syncthreads();
        int g = r >> 3, j = r & 7;
        const float* wr = Whh + ((long)dir*2048 + g*512 + hgrp*8 + j) * 512;
#pragma unroll 4
        for (int k = 0; k < 512; k += 8) {
            float w8[8];
            *(float4*)&w8[0] = *(const float4*)(wr + k);
            *(float4*)&w8[4] = *(const float4*)(wr + k + 4);
#pragma unroll
            for (int kk = 0; kk < 8; kk++) {
                float2 hv = *(const float2*)&hs[k+kk][2*q];
                a0 = fmaf(w8[kk], hv.x, a0);
                a1 = fmaf(w8[kk], hv.y, a1);
            }
        }
    }
    sg[r][2*q] = a0; sg[r][2*q+1] = a1;
    __syncthreads();

    if (tid < 128) {
        int j = tid >> 4, b = tid & 15;
        int hd = hgrp*8 + j;
        long xb = ((long)s*BA + b)*4096 + dir*2048 + hd;
        float gi = sg[j     ][b] + xg[xb];
        float gf = sg[8  + j][b] + xg[xb + 512];
        float gg = sg[16 + j][b] + xg[xb + 1024];
        float go = sg[24 + j][b] + xg[xb + 1536];
        int ci = dir*(BA*HD2) + b*HD2 + hd;
        float cc = step ? c[ci] : 0.f;
        float cn = sigf(gf)*cc + sigf(gi)*tanhf(gg);
        float hn = sigf(go)*tanhf(cn);
        c[ci] = cn; hout[ci] = hn;
        y[((long)s*BA + b)*HID + dir*512 + hd] = hn;
        if (step == SL-1) {
            h0l[b*HID + dir*512 + hd] = hn;
            c0l[b*HID + dir*512 + hd] = cn;
        }
    }
}

// ==== decoder mm core: m16n8k8 tf32 MMA (M=16 batch, 128 rows, 128 k) =======
// Wt: bf16 [128][136] smem; xst: tf32 [16][132] smem. Writes part[slice][row][b].
__device__ __forceinline__ void mm_mma_core(
    const __nv_bfloat16 (*Wt)[136], const unsigned (*xst)[132],
    float* __restrict__ part, long pbase, int tid)
{
    int warp = tid >> 5, lane = tid & 31;
    int g = lane >> 2, tg = lane & 3;
    float acc[2][4];
#pragma unroll
    for (int nt = 0; nt < 2; nt++)
#pragma unroll
        for (int i = 0; i < 4; i++) acc[nt][i] = 0.f;

#pragma unroll
    for (int ks = 0; ks < 16; ks++) {
        int kb = ks*8;
        unsigned a0 = xst[g  ][kb+tg];
        unsigned a1 = xst[g+8][kb+tg];
        unsigned a2 = xst[g  ][kb+tg+4];
        unsigned a3 = xst[g+8][kb+tg+4];
#pragma unroll
        for (int nt = 0; nt < 2; nt++) {
            int nb = warp*16 + nt*8;
            unsigned b0 = ((unsigned)*(const unsigned short*)&Wt[nb+g][kb+tg  ]) << 16;
            unsigned b1 = ((unsigned)*(const unsigned short*)&Wt[nb+g][kb+tg+4]) << 16;
            asm volatile(
                "mma.sync.aligned.m16n8k8.row.col.f32.tf32.tf32.f32 "
                "{%0,%1,%2,%3}, {%4,%5,%6,%7}, {%8,%9}, {%0,%1,%2,%3};"
                : "+f"(acc[nt][0]), "+f"(acc[nt][1]),
                  "+f"(acc[nt][2]), "+f"(acc[nt][3])
                : "r"(a0), "r"(a1), "r"(a2), "r"(a3), "r"(b0), "r"(b1));
        }
    }
#pragma unroll
    for (int nt = 0; nt < 2; nt++) {
        long nl = pbase + warp*16 + nt*8 + tg*2;
        part[nl*16 + g]          = acc[nt][0];
        part[(nl+1)*16 + g]      = acc[nt][1];
        part[nl*16 + g + 8]      = acc[nt][2];
        part[(nl+1)*16 + g + 8]  = acc[nt][3];
    }
}

// -------- decoder layer: MMA mm + per-rowgroup-ticket cell (+attn) ----------
__global__ __launch_bounds__(256, 4) void mmbf_cell_k(
    const __nv_bfloat16* __restrict__ W1, const __nv_bfloat16* __restrict__ W2,
    const float* __restrict__ x1, const float* __restrict__ x2,
    const float* __restrict__ pre, const float* __restrict__ b1,
    const float* __restrict__ b2,
    float* __restrict__ c, float* __restrict__ hout,
    int* rgc, int* attnc,
    const float* __restrict__ hA, const float* __restrict__ hsrc,
    float* __restrict__ ctx)
{
    __shared__ __align__(16) __nv_bfloat16 Wt[128][136];
    __shared__ __align__(16) unsigned xst[16][132];
    __shared__ int tick;
    int tid = threadIdx.x, bid = blockIdx.x;
    float* part = g_part;
    int slice = bid & 15, rg = bid >> 4;

    {
        int r0 = rg*128, k0 = slice*128;
        const __nv_bfloat16* W; const float* x; int ko;
        if (k0 < 1024) { W = W1; x = x1; ko = k0; }
        else           { W = W2; x = x2; ko = k0 - 1024; }
        uint4 wc[8];
#pragma unroll
        for (int i = 0; i < 8; i++) {
            int cidx = tid + i*256;
            int row = cidx >> 4, qq = cidx & 15;
            wc[i] = *(const uint4*)(W + (long)(r0+row)*1024 + ko + qq*8);
        }
        // x: 16 x 128 fp32 -> tf32 smem (2048 elems, 8/thread)
        float xr[8];
#pragma unroll
        for (int i = 0; i < 8; i++) {
            int e = tid + i*256;
            int b = e >> 7, kk = e & 127;
            xr[i] = __ldcg(x + b*1024 + ko + kk);
        }
#pragma unroll
        for (int i = 0; i < 8; i++) {
            int cidx = tid + i*256;
            int row = cidx >> 4, qq = cidx & 15;
            *(uint4*)&Wt[row][qq*8] = wc[i];
        }
#pragma unroll
        for (int i = 0; i < 8; i++) {
            int e = tid + i*256;
            int b = e >> 7, kk = e & 127;
            xst[b][kk] = cvt_tf32(xr[i]);
        }
        __syncthreads();
        mm_mma_core(Wt, xst, part, (long)slice*4096 + r0, tid);
    }
    __threadfence();
    __syncthreads();
    if (tid == 0) atomicAdd(&rgc[rg], 1);

    if (slice < 14) return;
    int cb = (slice - 14)*32 + rg;
    if (tid < 4) {
        int need = 8*tid + (cb >> 3);
        while (*(volatile int*)&rgc[need] < 16) ;
    }
    __syncthreads();
    {
        int idx = cb*256 + tid;
        int b = idx & 15, hd = idx >> 4;
        float g[4];
#pragma unroll
        for (int gi = 0; gi < 4; gi++) {
            int row = gi*HID + hd;
            float v;
            if (pre) v = pre[(long)b*4096 + row];
            else     v = b1[row] + b2[row];
#pragma unroll
            for (int sl = 0; sl < 16; sl++)
                v += __ldcg(part + ((long)sl*4096 + row)*16 + b);
            g[gi] = v;
        }
        int ci = b*HID + hd;
        float cc = c[ci];
        float cn = sigf(g[1])*cc + sigf(g[0])*tanhf(g[2]);
        c[ci] = cn;
        hout[ci] = sigf(g[3])*tanhf(cn);
    }
    if (!attnc) return;

    __threadfence();
    __syncthreads();
    if (tid == 0) tick = atomicAdd(attnc, 1);
    __syncthreads();
    int t2 = tick;
    if (t2 < 48) return;
    if (tid == 0) { while (*(volatile int*)attnc < 64) ; }
    __syncthreads();
    {
        int b = t2 - 48;
        float* h3s = (float*)&Wt[0][0];
        float* sc  = h3s + 1024;
        for (int i = tid; i < HID; i += 256) h3s[i] = __ldcg(hout + b*HID + i);
        __syncthreads();
        int w = tid >> 5, lane = tid & 31;
        for (int s = w; s < SL; s += 8) {
            const float* hp = hA + ((long)s*BA + b)*HID;
            float p = 0.f;
            for (int k = lane; k < HID; k += 32) p = fmaf(h3s[k], hp[k], p);
#pragma unroll
            for (int o = 16; o > 0; o >>= 1) p += __shfl_xor_sync(0xffffffffu, p, o);
            if (lane == 0) sc[s] = p;
        }
        __syncthreads();
        if (tid == 0) {
            float mx = sc[0];
            for (int s = 1; s < SL; s++) mx = fmaxf(mx, sc[s]);
            float sum = 0.f;
            for (int s = 0; s < SL; s++) { sc[s] = expf(sc[s]-mx); sum += sc[s]; }
            float inv = 1.f/sum;
            for (int s = 0; s < SL; s++) sc[s] *= inv;
        }
        __syncthreads();
        float4 acc = make_float4(0,0,0,0);
        int k = tid*4;
        for (int s = 0; s < SL; s++) {
            float ws = sc[s];
            float4 v = *(const float4*)(hsrc + ((long)s*BA + b)*HID + k);
            acc.x = fmaf(ws, v.x, acc.x); acc.y = fmaf(ws, v.y, acc.y);
            acc.z = fmaf(ws, v.z, acc.z); acc.w = fmaf(ws, v.w, acc.w);
        }
        *(float4*)(ctx + b*HID + k) = acc;
    }
}

// -------- h_tilde: MMA mm (128 blocks) + rowgroup-ticket tanh --------
__global__ __launch_bounds__(256, 4) void mmbf_ht_k(
    const __nv_bfloat16* __restrict__ W1, const __nv_bfloat16* __restrict__ W2,
    const float* __restrict__ x1, const float* __restrict__ x2,
    const float* __restrict__ bc,
    float* __restrict__ htl, float* __restrict__ hbt, int t, int* rgc)
{
    __shared__ __align__(16) __nv_bfloat16 Wt[128][136];
    __shared__ __align__(16) unsigned xst[16][132];
    int tid = threadIdx.x, bid = blockIdx.x;
    float* part = g_part;
    int slice = bid & 15, rg = bid >> 4;
    {
        int r0 = rg*128, k0 = slice*128;
        const __nv_bfloat16* W; const float* x; int ko;
        if (k0 < 1024) { W = W1; x = x1; ko = k0; }
        else           { W = W2; x = x2; ko = k0 - 1024; }
        uint4 wc[8];
#pragma unroll
        for (int i = 0; i < 8; i++) {
            int cidx = tid + i*256;
            int row = cidx >> 4, qq = cidx & 15;
            wc[i] = *(const uint4*)(W + (long)(r0+row)*1024 + ko + qq*8);
        }
        float xr[8];
#pragma unroll
        for (int i = 0; i < 8; i++) {
            int e = tid + i*256;
            int b = e >> 7, kk = e & 127;
            xr[i] = __ldcg(x + b*1024 + ko + kk);
        }
#pragma unroll
        for (int i = 0; i < 8; i++) {
            int cidx = tid + i*256;
            int row = cidx >> 4, qq = cidx & 15;
            *(uint4*)&Wt[row][qq*8] = wc[i];
        }
#pragma unroll
        for (int i = 0; i < 8; i++) {
            int e = tid + i*256;
            int b = e >> 7, kk = e & 127;
            xst[b][kk] = cvt_tf32(xr[i]);
        }
        __syncthreads();
        mm_mma_core(Wt, xst, part, (long)slice*1024 + r0, tid);
    }
    __threadfence();
    __syncthreads();
    if (tid == 0) atomicAdd(&rgc[rg], 1);

    if (slice < 8) return;
    int cb = (slice - 8)*8 + rg;
    if (tid == 0) { while (*(volatile int*)&rgc[cb >> 3] < 16) ; }
    __syncthreads();
    {
        int idx = cb*256 + tid;
        int b = idx & 15, hd = idx >> 4;
        float v = bc[hd];
#pragma unroll
        for (int sl = 0; sl < 16; sl++)
            v += __ldcg(part + ((long)sl*1024 + hd)*16 + b);
        float h = tanhf(v);
        htl[b*HID + hd] = h;
        hbt[((long)t*BA + b)*HID + hd] = h;
    }
}

// ---------------- log-softmax ----------------
__global__ __launch_bounds__(256) void lsm_k(float* __restrict__ out)
{
    __shared__ float red[256];
    long m = blockIdx.x;
    float* row = out + m*VOUT;
    int tid = threadIdx.x;
    float mx = -1e30f;
    for (int i = tid; i < VOUT/4; i += 256) {
        float4 v = *(const float4*)(row + i*4);
        mx = fmaxf(mx, fmaxf(fmaxf(v.x, v.y), fmaxf(v.z, v.w)));
    }
    red[tid] = mx; __syncthreads();
    for (int o = 128; o > 0; o >>= 1) { if (tid < o) red[tid] = fmaxf(red[tid], red[tid+o]); __syncthreads(); }
    mx = red[0]; __syncthreads();
    float sum = 0.f;
    for (int i = tid; i < VOUT/4; i += 256) {
        float4 v = *(const float4*)(row + i*4);
        sum += expf(v.x-mx)+expf(v.y-mx)+expf(v.z-mx)+expf(v.w-mx);
    }
    red[tid] = sum; __syncthreads();
    for (int o = 128; o > 0; o >>= 1) { if (tid < o) red[tid] += red[tid+o]; __syncthreads(); }
    float lse = mx + logf(red[0]);
    for (int i = tid; i < VOUT/4; i += 256) {
        float4 v = *(const float4*)(row + i*4);
        v.x -= lse; v.y -= lse; v.z -= lse; v.w -= lse;
        *(float4*)(row + i*4) = v;
    }
}

static float* sym(const void* s){ void* p = nullptr; cudaGetSymbolAddress(&p, s); return (float*)p; }

extern "C" void kernel_launch(void* const* d_in, const int* in_sizes, int n_in,
                              void* d_out, int out_size)
{
    const int*   src   = (const int*)  d_in[0];
    const int*   tgt   = (const int*)  d_in[1];
    const float* embS  = (const float*)d_in[2];
    const float* embD  = (const float*)d_in[3];
    const float* eWih  = (const float*)d_in[4];
    const float* eWhh  = (const float*)d_in[5];
    const float* ebih  = (const float*)d_in[6];
    const float* ebhh  = (const float*)d_in[7];
    const float* d0Wih = (const float*)d_in[8];
    const float* d0Whh = (const float*)d_in[9];
    const float* d0bih = (const float*)d_in[10];
    const float* d0bhh = (const float*)d_in[11];
    const float* dWih  = (const float*)d_in[12];
    const float* dWhh  = (const float*)d_in[13];
    const float* dbih  = (const float*)d_in[14];
    const float* dbhh  = (const float*)d_in[15];
    const float* Wattn = (const float*)d_in[16];
    const float* Wcat  = (const float*)d_in[17];
    const float* bcat  = (const float*)d_in[18];
    const float* Wout  = (const float*)d_in[19];
    const float* bout  = (const float*)d_in[20];
    float* out = (float*)d_out;

    float* encx = sym(g_encx);  float* ency = sym(g_ency);
    float* encxg = sym(g_encxg);
    float* ehA = sym(g_enchA);  float* ehB = sym(g_enchB);
    float* ecc = sym(g_encc);
    float* h0 = sym(g_h0);      float* c0 = sym(g_c0);
    float* demb = sym(g_demb);  float* pre0 = sym(g_pre0);
    float* dhA = sym(g_dhA);    float* dhB = sym(g_dhB);
    float* dc  = sym(g_dc);
    float* htl = sym(g_htl);    float* ctx = sym(g_ctx);
    float* hAp = sym(g_hA);     float* hbt = sym(g_hbt);
    __nv_bfloat16* wbf = (__nv_bfloat16*)sym(g_wbf);
    __nv_bfloat16* wout = (__nv_bfloat16*)sym(g_wout);
    int* ctrs = (int*)sym(g_ctrs);

    static cudaStream_t s2 = nullptr;
    static cudaEvent_t evf, evpre;
    if (!s2) {
        cudaStreamCreateWithFlags(&s2, cudaStreamNonBlocking);
        cudaEventCreateWithFlags(&evf, cudaEventDisableTiming);
        cudaEventCreateWithFlags(&evpre, cudaEventDisableTiming);
    }

    ctrz_k<<<40, 256>>>();
    cudaEventRecord(evf, 0);
    cudaStreamWaitEvent(s2, evf, 0);

    // ---- precompute on s2 (overlaps encoder on s0) ----
    {
        long n1 = 4194304L, n3 = 12582912L, nc = 1048576L;
        cvt_k <<<1024, 256, 0, s2>>>(wbf + OFF_W0H, d0Wih, 2048, 1024, 1024, n1);
        cvtf_k<<<1024, 256, 0, s2>>>(wbf + OFF_W0R, d0Whh, n1/4);
        cvtf_k<<<2048, 256, 0, s2>>>(wbf + OFF_WIH, dWih, n3/4);
        cvtf_k<<<2048, 256, 0, s2>>>(wbf + OFF_WHH, dWhh, n3/4);
        cvt_k <<<512, 256, 0, s2>>>(wbf + OFF_WC1, Wcat, 2048, 0, 1024, nc);
        cvt_k <<<512, 256, 0, s2>>>(wbf + OFF_WC2, Wcat, 2048, 1024, 1024, nc);
        cvtf_k<<<2048, 256, 0, s2>>>(wout, Wout, (long)VOUT*HID/4);
        embed_k<<<dim3(TL, BA), 256, 0, s2>>>(tgt, embD, demb, TL);
        gemm_tc_k<<<dim3(32, 7), 256, 0, s2>>>(demb, HID, d0Wih, 2048, d0bih, d0bhh,
                                               pre0, 4096, TL*BA, 4096, 1024);
    }
    cudaEventRecord(evpre, s2);

    // ---- encoder on s0 ----
    embed_k<<<dim3(SL, BA), 256>>>(src, embS, encx, SL);
    float* xin = encx; float* yout = ency;
    for (int l = 0; l < NL; l++) {
        gemm_tc_k<<<dim3(32, 7), 256>>>(xin, HID, eWih + (long)l*4096*1024, 1024,
                                        ebih + l*4096, ebhh + l*4096, encxg, 4096,
                                        SL*BA, 4096, 1024);
        float* hi = ehA; float* ho = ehB;
        const float* Whh = eWhh + (long)l*4096*512;
        for (int st = 0; st < SL; st++) {
            enc_fused_k<<<128, 256>>>(Whh, encxg, hi, ho, ecc, yout,
                                      h0 + (long)l*BA*HID, c0 + (long)l*BA*HID, st);
            float* tmp = hi; hi = ho; ho = tmp;
        }
        float* t = xin; xin = yout; yout = t;
    }
    float* hsrc = xin;

    gemm_k<<<dim3(8, 7), 256>>>(hsrc, HID, Wattn, 1024, 0, hAp, HID,
                                SL*BA, 1024, 1024);
    dinit_k<<<NL*BA*HID/256, 256>>>(dhA, h0, dc, c0, htl);
    cudaStreamWaitEvent(0, evpre, 0);

    // ---- decoder loop: 5 kernels/step ----
    for (int t = 0; t < TL; t++) {
        float* hprev = (t & 1) ? dhB : dhA;
        float* hcur  = (t & 1) ? dhA : dhB;
        int base = t*5*40;
        mmbf_cell_k<<<512, 256>>>(wbf + OFF_W0H, wbf + OFF_W0R, htl, hprev,
                                  pre0 + (long)t*BA*4096, nullptr, nullptr,
                                  dc, hcur,
                                  ctrs + base, nullptr, nullptr, nullptr, nullptr);
        for (int i = 0; i < NL-1; i++) {
            int last = (i == NL-2);
            int b2 = base + (i+1)*40;
            mmbf_cell_k<<<512, 256>>>(wbf + OFF_WIH + (long)i*4194304,
                                      wbf + OFF_WHH + (long)i*4194304,
                                      hcur + (long)i*BA*HID,
                                      hprev + (long)(i+1)*BA*HID,
                                      nullptr, dbih + i*4096, dbhh + i*4096,
                                      dc + (long)(i+1)*BA*HID,
                                      hcur + (long)(i+1)*BA*HID,
                                      ctrs + b2,
                                      last ? (ctrs + b2 + 32) : nullptr,
                                      last ? hAp : nullptr,
                                      last ? hsrc : nullptr,
                                      last ? ctx : nullptr);
        }
        mmbf_ht_k<<<128, 256>>>(wbf + OFF_WC1, wbf + OFF_WC2,
                                hcur + (long)3*BA*HID, ctx,
                                bcat, htl, hbt, t, ctrs + base + 4*40);
    }

    // ---- generator (serial, bf16 weights) ----
    gemm_tcb_k<<<dim3(250, 7), 256>>>(hbt, HID, wout, 1024, bout,
                                      out, VOUT, TL*BA, VOUT, HID, 0);
    lsm_k<<<TL*BA, 256>>>(out);
}

// round 17
// speedup vs baseline: 1.4708x; 1.1572x over previous
#include <cuda_runtime.h>
#include <cuda_bf16.h>
#include <math.h>

#define SL 50
#define TL 50
#define BA 16
#define HID 1024
#define HD2 512
#define NL 4
#define VOUT 32000

__device__ __align__(16) float g_encx [SL*BA*HID];
__device__ __align__(16) float g_ency [SL*BA*HID];
__device__ __align__(16) float g_encxg[SL*BA*4096];
__device__ __align__(16) float g_enchA[2*BA*HD2];
__device__ __align__(16) float g_enchB[2*BA*HD2];
__device__ __align__(16) float g_encc [2*BA*HD2];
__device__ __align__(16) float g_h0   [NL*BA*HID];
__device__ __align__(16) float g_c0   [NL*BA*HID];
__device__ __align__(16) float g_demb [TL*BA*HID];
__device__ __align__(16) float g_pre0 [TL*BA*4096];
__device__ __align__(16) float g_dhA  [NL*BA*HID];
__device__ __align__(16) float g_dhB  [NL*BA*HID];
__device__ __align__(16) float g_dc   [NL*BA*HID];
__device__ __align__(16) float g_htl  [BA*HID];
__device__ __align__(16) float g_ctx  [BA*HID];
__device__ __align__(16) float g_hA   [SL*BA*HID];
__device__ __align__(16) float g_hbt  [TL*BA*HID];   // [t][b][H]
__device__ __align__(16) float g_part [16*4096*16];
// decoder: [0,10000) stride 200/step; encoder rowgroup ctrs: [10240,16640)
__device__ int g_ctrs[16896];
#define OFF_W0H 0L
#define OFF_W0R 4194304L
#define OFF_WIH 8388608L
#define OFF_WHH 20971520L
#define OFF_WC1 33554432L
#define OFF_WC2 34603008L
__device__ __align__(16) __nv_bfloat16 g_wbf[35651584];
__device__ __align__(16) __nv_bfloat16 g_wout[(long)VOUT*HID];

__device__ __forceinline__ float sigf(float x){ return 1.f/(1.f+expf(-x)); }

__device__ __forceinline__ unsigned cvt_tf32(float f){
    unsigned u;
    asm("cvt.rna.tf32.f32 %0, %1;" : "=r"(u) : "f"(f));
    return u;
}

__global__ void ctrz_k(){ g_ctrs[threadIdx.x + blockIdx.x*256] = 0; }

__global__ void embed_k(const int* __restrict__ idx, const float* __restrict__ W,
                        float* __restrict__ out, int slen){
    int s = blockIdx.x, b = blockIdx.y;
    long tok = idx[b*slen + s];
    const float4* sp = (const float4*)(W + tok*1024);
    float4* dp = (float4*)(out + ((long)s*BA + b)*1024);
    for (int i = threadIdx.x; i < 256; i += blockDim.x) dp[i] = sp[i];
}

__global__ void dinit_k(float* __restrict__ dh, const float* __restrict__ h0,
                        float* __restrict__ dcc, const float* __restrict__ c0,
                        float* __restrict__ htl){
    int i = blockIdx.x*256 + threadIdx.x;
    dh[i] = h0[i];
    dcc[i] = c0[i];
    if (i < BA*HID) htl[i] = 0.f;
}

__global__ void cvtf_k(__nv_bfloat16* __restrict__ dst, const float* __restrict__ src,
                       long total4){
    long stride = (long)gridDim.x*blockDim.x;
    for (long i = (long)blockIdx.x*blockDim.x + threadIdx.x; i < total4; i += stride){
        float4 v = ((const float4*)src)[i];
        ((__nv_bfloat162*)dst)[2*i]   = __floats2bfloat162_rn(v.x, v.y);
        ((__nv_bfloat162*)dst)[2*i+1] = __floats2bfloat162_rn(v.z, v.w);
    }
}
__global__ void cvt_k(__nv_bfloat16* __restrict__ dst, const float* __restrict__ src,
                      int srcld, int col0, int ncols, long total){
    long stride = (long)gridDim.x*blockDim.x;
    for (long i = (long)blockIdx.x*blockDim.x + threadIdx.x; i < total; i += stride){
        long r = i / ncols, cc = i - r*ncols;
        dst[i] = __float2bfloat16(src[r*srcld + col0 + cc]);
    }
}

// ---------- tf32 tensor-core GEMM (fp32 A, fp32 B[N,K]) ----------
__global__ __launch_bounds__(256) void gemm_tc_k(
    const float* __restrict__ A, int lda,
    const float* __restrict__ B, int ldb,
    const float* __restrict__ b1, const float* __restrict__ b2,
    float* __restrict__ C, int ldc, int M, int N, int K)
{
    __shared__ unsigned As[128][36];
    __shared__ unsigned Bs[128][36];
    int tid = threadIdx.x;
    int m0 = blockIdx.y*128, n0 = blockIdx.x*128;
    int warp = tid >> 5, lane = tid & 31;
    int wm = warp >> 2, wn = warp & 3;
    int g = lane >> 2, tg = lane & 3;
    float acc[4][4][4];
#pragma unroll
    for (int mt = 0; mt < 4; mt++)
#pragma unroll
        for (int nt = 0; nt < 4; nt++)
#pragma unroll
            for (int i = 0; i < 4; i++) acc[mt][nt][i] = 0.f;

    for (int k0 = 0; k0 < K; k0 += 32) {
#pragma unroll
        for (int i = 0; i < 4; i++) {
            int e = tid + i*256;
            int m = e >> 3, kq = e & 7;
            float4 v = make_float4(0,0,0,0);
            if (m0 + m < M) v = *(const float4*)(A + (long)(m0+m)*lda + k0 + kq*4);
            unsigned* d = &As[m][kq*4];
            d[0]=cvt_tf32(v.x); d[1]=cvt_tf32(v.y); d[2]=cvt_tf32(v.z); d[3]=cvt_tf32(v.w);
        }
#pragma unroll
        for (int i = 0; i < 4; i++) {
            int e = tid + i*256;
            int n = e >> 3, kq = e & 7;
            float4 v = *(const float4*)(B + (long)(n0+n)*ldb + k0 + kq*4);
            unsigned* d = &Bs[n][kq*4];
            d[0]=cvt_tf32(v.x); d[1]=cvt_tf32(v.y); d[2]=cvt_tf32(v.z); d[3]=cvt_tf32(v.w);
        }
        __syncthreads();
#pragma unroll
        for (int ks = 0; ks < 4; ks++) {
            int kb = ks*8;
            unsigned a[4][4], b[4][2];
#pragma unroll
            for (int mt = 0; mt < 4; mt++) {
                int mb = wm*64 + mt*16;
                a[mt][0] = As[mb+g  ][kb+tg];
                a[mt][1] = As[mb+g+8][kb+tg];
                a[mt][2] = As[mb+g  ][kb+tg+4];
                a[mt][3] = As[mb+g+8][kb+tg+4];
            }
#pragma unroll
            for (int nt = 0; nt < 4; nt++) {
                int nb = wn*32 + nt*8;
                b[nt][0] = Bs[nb+g][kb+tg];
                b[nt][1] = Bs[nb+g][kb+tg+4];
            }
#pragma unroll
            for (int mt = 0; mt < 4; mt++)
#pragma unroll
                for (int nt = 0; nt < 4; nt++)
                    asm volatile(
                        "mma.sync.aligned.m16n8k8.row.col.f32.tf32.tf32.f32 "
                        "{%0,%1,%2,%3}, {%4,%5,%6,%7}, {%8,%9}, {%0,%1,%2,%3};"
                        : "+f"(acc[mt][nt][0]), "+f"(acc[mt][nt][1]),
                          "+f"(acc[mt][nt][2]), "+f"(acc[mt][nt][3])
                        : "r"(a[mt][0]), "r"(a[mt][1]), "r"(a[mt][2]), "r"(a[mt][3]),
                          "r"(b[nt][0]), "r"(b[nt][1]));
        }
        __syncthreads();
    }
#pragma unroll
    for (int mt = 0; mt < 4; mt++) {
#pragma unroll
        for (int h = 0; h < 2; h++) {
            int m = m0 + wm*64 + mt*16 + g + h*8;
            if (m < M) {
#pragma unroll
                for (int nt = 0; nt < 4; nt++) {
                    int n = n0 + wn*32 + nt*8 + tg*2;
                    float v0 = acc[mt][nt][h*2+0];
                    float v1 = acc[mt][nt][h*2+1];
                    if (b1) { v0 += b1[n]; v1 += b1[n+1]; }
                    if (b2) { v0 += b2[n]; v1 += b2[n+1]; }
                    C[(long)m*ldc + n]     = v0;
                    C[(long)m*ldc + n + 1] = v1;
                }
            }
        }
    }
}

// ---------- tf32 GEMM with bf16 B (generator; scattered output rows) --------
__global__ __launch_bounds__(256) void gemm_tcb_k(
    const float* __restrict__ A, int lda,
    const __nv_bfloat16* __restrict__ B, int ldb,
    const float* __restrict__ b1,
    float* __restrict__ C, int ldc, int M, int N, int K, int t0)
{
    __shared__ unsigned As[128][36];
    __shared__ unsigned Bs[128][36];
    int tid = threadIdx.x;
    int m0 = blockIdx.y*128, n0 = blockIdx.x*128;
    int warp = tid >> 5, lane = tid & 31;
    int wm = warp >> 2, wn = warp & 3;
    int g = lane >> 2, tg = lane & 3;
    float acc[4][4][4];
#pragma unroll
    for (int mt = 0; mt < 4; mt++)
#pragma unroll
        for (int nt = 0; nt < 4; nt++)
#pragma unroll
            for (int i = 0; i < 4; i++) acc[mt][nt][i] = 0.f;

    for (int k0 = 0; k0 < K; k0 += 32) {
#pragma unroll
        for (int i = 0; i < 4; i++) {
            int e = tid + i*256;
            int m = e >> 3, kq = e & 7;
            float4 v = make_float4(0,0,0,0);
            if (m0 + m < M) v = *(const float4*)(A + (long)(m0+m)*lda + k0 + kq*4);
            unsigned* d = &As[m][kq*4];
            d[0]=cvt_tf32(v.x); d[1]=cvt_tf32(v.y); d[2]=cvt_tf32(v.z); d[3]=cvt_tf32(v.w);
        }
#pragma unroll
        for (int i = 0; i < 2; i++) {
            int e = tid + i*256;
            int n = e >> 2, ch = e & 3;
            uint4 raw = __ldcs((const uint4*)(B + (long)(n0+n)*ldb + k0 + ch*8));
            const __nv_bfloat162* p = (const __nv_bfloat162*)&raw;
            unsigned* d = &Bs[n][ch*8];
#pragma unroll
            for (int j = 0; j < 4; j++) {
                float2 f = __bfloat1622float2(p[j]);
                d[2*j]   = cvt_tf32(f.x);
                d[2*j+1] = cvt_tf32(f.y);
            }
        }
        __syncthreads();
#pragma unroll
        for (int ks = 0; ks < 4; ks++) {
            int kb = ks*8;
            unsigned a[4][4], b[4][2];
#pragma unroll
            for (int mt = 0; mt < 4; mt++) {
                int mb = wm*64 + mt*16;
                a[mt][0] = As[mb+g  ][kb+tg];
                a[mt][1] = As[mb+g+8][kb+tg];
                a[mt][2] = As[mb+g  ][kb+tg+4];
                a[mt][3] = As[mb+g+8][kb+tg+4];
            }
#pragma unroll
            for (int nt = 0; nt < 4; nt++) {
                int nb = wn*32 + nt*8;
                b[nt][0] = Bs[nb+g][kb+tg];
                b[nt][1] = Bs[nb+g][kb+tg+4];
            }
#pragma unroll
            for (int mt = 0; mt < 4; mt++)
#pragma unroll
                for (int nt = 0; nt < 4; nt++)
                    asm volatile(
                        "mma.sync.aligned.m16n8k8.row.col.f32.tf32.tf32.f32 "
                        "{%0,%1,%2,%3}, {%4,%5,%6,%7}, {%8,%9}, {%0,%1,%2,%3};"
                        : "+f"(acc[mt][nt][0]), "+f"(acc[mt][nt][1]),
                          "+f"(acc[mt][nt][2]), "+f"(acc[mt][nt][3])
                        : "r"(a[mt][0]), "r"(a[mt][1]), "r"(a[mt][2]), "r"(a[mt][3]),
                          "r"(b[nt][0]), "r"(b[nt][1]));
        }
        __syncthreads();
    }
#pragma unroll
    for (int mt = 0; mt < 4; mt++) {
#pragma unroll
        for (int h = 0; h < 2; h++) {
            int m = m0 + wm*64 + mt*16 + g + h*8;
            if (m < M) {
                long crow = (long)(m & 15)*TL + t0 + (m >> 4);
#pragma unroll
                for (int nt = 0; nt < 4; nt++) {
                    int n = n0 + wn*32 + nt*8 + tg*2;
                    C[crow*ldc + n]     = acc[mt][nt][h*2+0] + b1[n];
                    C[crow*ldc + n + 1] = acc[mt][nt][h*2+1] + b1[n+1];
                }
            }
        }
    }
}

// ---------------- scalar fp32 GEMM (small hA GEMM only) ---------------------
__global__ __launch_bounds__(256) void gemm_k(
    const float* __restrict__ A, int lda,
    const float* __restrict__ B, int ldb, int transB,
    float* __restrict__ C, int ldc, int M, int N, int K)
{
    __shared__ float As[16][132];
    __shared__ float Bs[16][132];
    int m0 = blockIdx.y*128, n0 = blockIdx.x*128;
    int tid = threadIdx.x, tx = tid & 15, ty = tid >> 4;
    float acc[8][8];
#pragma unroll
    for (int i = 0; i < 8; i++)
#pragma unroll
        for (int j = 0; j < 8; j++) acc[i][j] = 0.f;

    for (int k0 = 0; k0 < K; k0 += 16) {
#pragma unroll
        for (int i = 0; i < 2; i++) {
            int e = tid + i*256, m = e >> 2, kq = e & 3;
            float4 v = make_float4(0,0,0,0);
            if (m0 + m < M) v = *(const float4*)(A + (long)(m0+m)*lda + k0 + kq*4);
            As[kq*4+0][m]=v.x; As[kq*4+1][m]=v.y; As[kq*4+2][m]=v.z; As[kq*4+3][m]=v.w;
        }
        if (transB) {
#pragma unroll
            for (int i = 0; i < 2; i++) {
                int e = tid + i*256, n = e >> 2, kq = e & 3;
                float4 v = *(const float4*)(B + (long)(n0+n)*ldb + k0 + kq*4);
                Bs[kq*4+0][n]=v.x; Bs[kq*4+1][n]=v.y; Bs[kq*4+2][n]=v.z; Bs[kq*4+3][n]=v.w;
            }
        } else {
#pragma unroll
            for (int i = 0; i < 2; i++) {
                int e = tid + i*256, kk = e >> 5, nq = e & 31;
                *(float4*)&Bs[kk][nq*4] = *(const float4*)(B + (long)(k0+kk)*ldb + n0 + nq*4);
            }
        }
        __syncthreads();
#pragma unroll
        for (int kk = 0; kk < 16; kk++) {
            float a[8], bv[8];
            *(float4*)&a[0] = *(float4*)&As[kk][ty*8];
            *(float4*)&a[4] = *(float4*)&As[kk][ty*8+4];
            *(float4*)&bv[0] = *(float4*)&Bs[kk][tx*8];
            *(float4*)&bv[4] = *(float4*)&Bs[kk][tx*8+4];
#pragma unroll
            for (int i = 0; i < 8; i++)
#pragma unroll
                for (int j = 0; j < 8; j++) acc[i][j] = fmaf(a[i], bv[j], acc[i][j]);
        }
        __syncthreads();
    }
#pragma unroll
    for (int i = 0; i < 8; i++) {
        int m = m0 + ty*8 + i;
        if (m < M) {
            float* Cr = C + (long)m*ldc + n0 + tx*8;
#pragma unroll
            for (int j = 0; j < 8; j++) Cr[j] = acc[i][j];
        }
    }
}

// ==== MMA core, bf16 smem weights (decoder) =================================
__device__ __forceinline__ void mm_mma_core(
    const __nv_bfloat16 (*Wt)[136], const unsigned (*xst)[132],
    float* __restrict__ part, long pbase, int tid)
{
    int warp = tid >> 5, lane = tid & 31;
    int g = lane >> 2, tg = lane & 3;
    float acc[2][4];
#pragma unroll
    for (int nt = 0; nt < 2; nt++)
#pragma unroll
        for (int i = 0; i < 4; i++) acc[nt][i] = 0.f;

#pragma unroll
    for (int ks = 0; ks < 16; ks++) {
        int kb = ks*8;
        unsigned a0 = xst[g  ][kb+tg];
        unsigned a1 = xst[g+8][kb+tg];
        unsigned a2 = xst[g  ][kb+tg+4];
        unsigned a3 = xst[g+8][kb+tg+4];
#pragma unroll
        for (int nt = 0; nt < 2; nt++) {
            int nb = warp*16 + nt*8;
            unsigned b0 = ((unsigned)*(const unsigned short*)&Wt[nb+g][kb+tg  ]) << 16;
            unsigned b1 = ((unsigned)*(const unsigned short*)&Wt[nb+g][kb+tg+4]) << 16;
            asm volatile(
                "mma.sync.aligned.m16n8k8.row.col.f32.tf32.tf32.f32 "
                "{%0,%1,%2,%3}, {%4,%5,%6,%7}, {%8,%9}, {%0,%1,%2,%3};"
                : "+f"(acc[nt][0]), "+f"(acc[nt][1]),
                  "+f"(acc[nt][2]), "+f"(acc[nt][3])
                : "r"(a0), "r"(a1), "r"(a2), "r"(a3), "r"(b0), "r"(b1));
        }
    }
#pragma unroll
    for (int nt = 0; nt < 2; nt++) {
        long nl = pbase + warp*16 + nt*8 + tg*2;
        part[nl*16 + g]          = acc[nt][0];
        part[(nl+1)*16 + g]      = acc[nt][1];
        part[nl*16 + g + 8]      = acc[nt][2];
        part[(nl+1)*16 + g + 8]  = acc[nt][3];
    }
}

// ==== MMA core, tf32 smem weights (encoder) =================================
__device__ __forceinline__ void mm_mma_core32(
    const unsigned (*Wt)[132], const unsigned (*xst)[132],
    float* __restrict__ part, long pbase, int tid)
{
    int warp = tid >> 5, lane = tid & 31;
    int g = lane >> 2, tg = lane & 3;
    float acc[2][4];
#pragma unroll
    for (int nt = 0; nt < 2; nt++)
#pragma unroll
        for (int i = 0; i < 4; i++) acc[nt][i] = 0.f;

#pragma unroll
    for (int ks = 0; ks < 16; ks++) {
        int kb = ks*8;
        unsigned a0 = xst[g  ][kb+tg];
        unsigned a1 = xst[g+8][kb+tg];
        unsigned a2 = xst[g  ][kb+tg+4];
        unsigned a3 = xst[g+8][kb+tg+4];
#pragma unroll
        for (int nt = 0; nt < 2; nt++) {
            int nb = warp*16 + nt*8;
            unsigned b0 = Wt[nb+g][kb+tg];
            unsigned b1 = Wt[nb+g][kb+tg+4];
            asm volatile(
                "mma.sync.aligned.m16n8k8.row.col.f32.tf32.tf32.f32 "
                "{%0,%1,%2,%3}, {%4,%5,%6,%7}, {%8,%9}, {%0,%1,%2,%3};"
                : "+f"(acc[nt][0]), "+f"(acc[nt][1]),
                  "+f"(acc[nt][2]), "+f"(acc[nt][3])
                : "r"(a0), "r"(a1), "r"(a2), "r"(a3), "r"(b0), "r"(b1));
        }
    }
#pragma unroll
    for (int nt = 0; nt < 2; nt++) {
        long nl = pbase + warp*16 + nt*8 + tg*2;
        part[nl*16 + g]          = acc[nt][0];
        part[(nl+1)*16 + g]      = acc[nt][1];
        part[nl*16 + g + 8]      = acc[nt][2];
        part[(nl+1)*16 + g + 8]  = acc[nt][3];
    }
}

// ==== encoder step: MMA matvec + rowgroup-ticket LSTM cell, both dirs =======
// grid 128: slice = bid&3 (K=128 of 512), rg = bid>>2 (128 rows of 4096).
// rows: dir*2048 + gate*512 + hd. cell on slice>=2 blocks (64).
__global__ __launch_bounds__(256, 2) void enc_mma_k(
    const float* __restrict__ Whh, const float* __restrict__ xg,
    const float* __restrict__ hin, float* __restrict__ hout,
    float* __restrict__ c, float* __restrict__ y,
    float* __restrict__ h0l, float* __restrict__ c0l, int step, int* rgc)
{
    __shared__ __align__(16) unsigned Wt[128][132];
    __shared__ __align__(16) unsigned xst[16][132];
    int tid = threadIdx.x, bid = blockIdx.x;
    int slice = bid & 3, rg = bid >> 2;
    float* part = g_part;

    if (step > 0) {
        int dir = rg >> 4;
        int r0 = rg*128, ko = slice*128;
        const float* x = hin + dir*(BA*HD2);
        float4 wc[16];
#pragma unroll
        for (int i = 0; i < 16; i++) {
            int cidx = tid + i*256;            // 4096 float4 = 128 rows x 32
            int row = cidx >> 5, q = cidx & 31;
            wc[i] = *(const float4*)(Whh + (long)(r0+row)*512 + ko + q*4);
        }
        float xr[8];
#pragma unroll
        for (int i = 0; i < 8; i++) {
            int e = tid + i*256;               // 16 x 128
            int b = e >> 7, kk = e & 127;
            xr[i] = x[b*HD2 + ko + kk];
        }
#pragma unroll
        for (int i = 0; i < 16; i++) {
            int cidx = tid + i*256;
            int row = cidx >> 5, q = cidx & 31;
            uint4 u;
            u.x = cvt_tf32(wc[i].x); u.y = cvt_tf32(wc[i].y);
            u.z = cvt_tf32(wc[i].z); u.w = cvt_tf32(wc[i].w);
            *(uint4*)&Wt[row][q*4] = u;
        }
#pragma unroll
        for (int i = 0; i < 8; i++) {
            int e = tid + i*256;
            int b = e >> 7, kk = e & 127;
            xst[b][kk] = cvt_tf32(xr[i]);
        }
        __syncthreads();
        mm_mma_core32(Wt, xst, part, (long)slice*4096 + r0, tid);
        __threadfence();
        __syncthreads();
        if (tid == 0) atomicAdd(&rgc[rg], 1);
    }

    if (slice < 2) return;
    int cb = (slice - 2)*32 + rg;              // 0..63
    if (step > 0) {
        int dirb = cb >> 5;
        int sub = (cb & 31) >> 3;
        if (tid < 4) {
            int need = dirb*16 + tid*4 + sub;
            while (*(volatile int*)&rgc[need] < 4) ;
        }
        __syncthreads();
    }
    {
        int idx = cb*256 + tid;
        int b = idx & 15, hd2 = idx >> 4;      // hd2 0..1023
        int dir = hd2 >> 9, hd = hd2 & 511;
        int s = dir ? (SL-1-step) : step;
        long xb = ((long)s*BA + b)*4096 + dir*2048 + hd;
        float g4[4];
#pragma unroll
        for (int gi = 0; gi < 4; gi++) {
            float v = xg[xb + gi*512];
            if (step > 0) {
                long row = (long)dir*2048 + gi*512 + hd;
#pragma unroll
                for (int sl = 0; sl < 4; sl++)
                    v += __ldcg(part + ((long)sl*4096 + row)*16 + b);
            }
            g4[gi] = v;
        }
        int ci = dir*(BA*HD2) + b*HD2 + hd;
        float cc = step ? c[ci] : 0.f;
        float cn = sigf(g4[1])*cc + sigf(g4[0])*tanhf(g4[2]);
        float hn = sigf(g4[3])*tanhf(cn);
        c[ci] = cn; hout[ci] = hn;
        y[((long)s*BA + b)*HID + dir*512 + hd] = hn;
        if (step == SL-1) {
            h0l[b*HID + dir*512 + hd] = hn;
            c0l[b*HID + dir*512 + hd] = cn;
        }
    }
}

// -------- decoder layer: MMA mm + per-rowgroup-ticket cell (+attn) ----------
__global__ __launch_bounds__(256, 4) void mmbf_cell_k(
    const __nv_bfloat16* __restrict__ W1, const __nv_bfloat16* __restrict__ W2,
    const float* __restrict__ x1, const float* __restrict__ x2,
    const float* __restrict__ pre, const float* __restrict__ b1,
    const float* __restrict__ b2,
    float* __restrict__ c, float* __restrict__ hout,
    int* rgc, int* attnc,
    const float* __restrict__ hA, const float* __restrict__ hsrc,
    float* __restrict__ ctx)
{
    __shared__ __align__(16) __nv_bfloat16 Wt[128][136];
    __shared__ __align__(16) unsigned xst[16][132];
    __shared__ int tick;
    int tid = threadIdx.x, bid = blockIdx.x;
    float* part = g_part;
    int slice = bid & 15, rg = bid >> 4;

    {
        int r0 = rg*128, k0 = slice*128;
        const __nv_bfloat16* W; const float* x; int ko;
        if (k0 < 1024) { W = W1; x = x1; ko = k0; }
        else           { W = W2; x = x2; ko = k0 - 1024; }
        uint4 wc[8];
#pragma unroll
        for (int i = 0; i < 8; i++) {
            int cidx = tid + i*256;
            int row = cidx >> 4, qq = cidx & 15;
            wc[i] = *(const uint4*)(W + (long)(r0+row)*1024 + ko + qq*8);
        }
        float xr[8];
#pragma unroll
        for (int i = 0; i < 8; i++) {
            int e = tid + i*256;
            int b = e >> 7, kk = e & 127;
            xr[i] = __ldcg(x + b*1024 + ko + kk);
        }
#pragma unroll
        for (int i = 0; i < 8; i++) {
            int cidx = tid + i*256;
            int row = cidx >> 4, qq = cidx & 15;
            *(uint4*)&Wt[row][qq*8] = wc[i];
        }
#pragma unroll
        for (int i = 0; i < 8; i++) {
            int e = tid + i*256;
            int b = e >> 7, kk = e & 127;
            xst[b][kk] = cvt_tf32(xr[i]);
        }
        __syncthreads();
        mm_mma_core(Wt, xst, part, (long)slice*4096 + r0, tid);
    }
    __threadfence();
    __syncthreads();
    if (tid == 0) atomicAdd(&rgc[rg], 1);

    if (slice < 14) return;
    int cb = (slice - 14)*32 + rg;
    if (tid < 4) {
        int need = 8*tid + (cb >> 3);
        while (*(volatile int*)&rgc[need] < 16) ;
    }
    __syncthreads();
    {
        int idx = cb*256 + tid;
        int b = idx & 15, hd = idx >> 4;
        float g[4];
#pragma unroll
        for (int gi = 0; gi < 4; gi++) {
            int row = gi*HID + hd;
            float v;
            if (pre) v = pre[(long)b*4096 + row];
            else     v = b1[row] + b2[row];
#pragma unroll
            for (int sl = 0; sl < 16; sl++)
                v += __ldcg(part + ((long)sl*4096 + row)*16 + b);
            g[gi] = v;
        }
        int ci = b*HID + hd;
        float cc = c[ci];
        float cn = sigf(g[1])*cc + sigf(g[0])*tanhf(g[2]);
        c[ci] = cn;
        hout[ci] = sigf(g[3])*tanhf(cn);
    }
    if (!attnc) return;

    __threadfence();
    __syncthreads();
    if (tid == 0) tick = atomicAdd(attnc, 1);
    __syncthreads();
    int t2 = tick;
    if (t2 < 48) return;
    if (tid == 0) { while (*(volatile int*)attnc < 64) ; }
    __syncthreads();
    {
        int b = t2 - 48;
        float* h3s = (float*)&Wt[0][0];
        float* sc  = h3s + 1024;
        for (int i = tid; i < HID; i += 256) h3s[i] = __ldcg(hout + b*HID + i);
        __syncthreads();
        int w = tid >> 5, lane = tid & 31;
        for (int s = w; s < SL; s += 8) {
            const float* hp = hA + ((long)s*BA + b)*HID;
            float p = 0.f;
            for (int k = lane; k < HID; k += 32) p = fmaf(h3s[k], hp[k], p);
#pragma unroll
            for (int o = 16; o > 0; o >>= 1) p += __shfl_xor_sync(0xffffffffu, p, o);
            if (lane == 0) sc[s] = p;
        }
        __syncthreads();
        if (tid == 0) {
            float mx = sc[0];
            for (int s = 1; s < SL; s++) mx = fmaxf(mx, sc[s]);
            float sum = 0.f;
            for (int s = 0; s < SL; s++) { sc[s] = expf(sc[s]-mx); sum += sc[s]; }
            float inv = 1.f/sum;
            for (int s = 0; s < SL; s++) sc[s] *= inv;
        }
        __syncthreads();
        float4 acc = make_float4(0,0,0,0);
        int k = tid*4;
        for (int s = 0; s < SL; s++) {
            float ws = sc[s];
            float4 v = *(const float4*)(hsrc + ((long)s*BA + b)*HID + k);
            acc.x = fmaf(ws, v.x, acc.x); acc.y = fmaf(ws, v.y, acc.y);
            acc.z = fmaf(ws, v.z, acc.z); acc.w = fmaf(ws, v.w, acc.w);
        }
        *(float4*)(ctx + b*HID + k) = acc;
    }
}

// -------- h_tilde: MMA mm (128 blocks) + rowgroup-ticket tanh --------
__global__ __launch_bounds__(256, 4) void mmbf_ht_k(
    const __nv_bfloat16* __restrict__ W1, const __nv_bfloat16* __restrict__ W2,
    const float* __restrict__ x1, const float* __restrict__ x2,
    const float* __restrict__ bc,
    float* __restrict__ htl, float* __restrict__ hbt, int t, int* rgc)
{
    __shared__ __align__(16) __nv_bfloat16 Wt[128][136];
    __shared__ __align__(16) unsigned xst[16][132];
    int tid = threadIdx.x, bid = blockIdx.x;
    float* part = g_part;
    int slice = bid & 15, rg = bid >> 4;
    {
        int r0 = rg*128, k0 = slice*128;
        const __nv_bfloat16* W; const float* x; int ko;
        if (k0 < 1024) { W = W1; x = x1; ko = k0; }
        else           { W = W2; x = x2; ko = k0 - 1024; }
        uint4 wc[8];
#pragma unroll
        for (int i = 0; i < 8; i++) {
            int cidx = tid + i*256;
            int row = cidx >> 4, qq = cidx & 15;
            wc[i] = *(const uint4*)(W + (long)(r0+row)*1024 + ko + qq*8);
        }
        float xr[8];
#pragma unroll
        for (int i = 0; i < 8; i++) {
            int e = tid + i*256;
            int b = e >> 7, kk = e & 127;
            xr[i] = __ldcg(x + b*1024 + ko + kk);
        }
#pragma unroll
        for (int i = 0; i < 8; i++) {
            int cidx = tid + i*256;
            int row = cidx >> 4, qq = cidx & 15;
            *(uint4*)&Wt[row][qq*8] = wc[i];
        }
#pragma unroll
        for (int i = 0; i < 8; i++) {
            int e = tid + i*256;
            int b = e >> 7, kk = e & 127;
            xst[b][kk] = cvt_tf32(xr[i]);
        }
        __syncthreads();
        mm_mma_core(Wt, xst, part, (long)slice*1024 + r0, tid);
    }
    __threadfence();
    __syncthreads();
    if (tid == 0) atomicAdd(&rgc[rg], 1);

    if (slice < 8) return;
    int cb = (slice - 8)*8 + rg;
    if (tid == 0) { while (*(volatile int*)&rgc[cb >> 3] < 16) ; }
    __syncthreads();
    {
        int idx = cb*256 + tid;
        int b = idx & 15, hd = idx >> 4;
        float v = bc[hd];
#pragma unroll
        for (int sl = 0; sl < 16; sl++)
            v += __ldcg(part + ((long)sl*1024 + hd)*16 + b);
        float h = tanhf(v);
        htl[b*HID + hd] = h;
        hbt[((long)t*BA + b)*HID + hd] = h;
    }
}

// ---------------- log-softmax ----------------
__global__ __launch_bounds__(256) void lsm_k(float* __restrict__ out)
{
    __shared__ float red[256];
    long m = blockIdx.x;
    float* row = out + m*VOUT;
    int tid = threadIdx.x;
    float mx = -1e30f;
    for (int i = tid; i < VOUT/4; i += 256) {
        float4 v = *(const float4*)(row + i*4);
        mx = fmaxf(mx, fmaxf(fmaxf(v.x, v.y), fmaxf(v.z, v.w)));
    }
    red[tid] = mx; __syncthreads();
    for (int o = 128; o > 0; o >>= 1) { if (tid < o) red[tid] = fmaxf(red[tid], red[tid+o]); __syncthreads(); }
    mx = red[0]; __syncthreads();
    float sum = 0.f;
    for (int i = tid; i < VOUT/4; i += 256) {
        float4 v = *(const float4*)(row + i*4);
        sum += expf(v.x-mx)+expf(v.y-mx)+expf(v.z-mx)+expf(v.w-mx);
    }
    red[tid] = sum; __syncthreads();
    for (int o = 128; o > 0; o >>= 1) { if (tid < o) red[tid] += red[tid+o]; __syncthreads(); }
    float lse = mx + logf(red[0]);
    for (int i = tid; i < VOUT/4; i += 256) {
        float4 v = *(const float4*)(row + i*4);
        v.x -= lse; v.y -= lse; v.z -= lse; v.w -= lse;
        *(float4*)(row + i*4) = v;
    }
}

static float* sym(const void* s){ void* p = nullptr; cudaGetSymbolAddress(&p, s); return (float*)p; }

extern "C" void kernel_launch(void* const* d_in, const int* in_sizes, int n_in,
                              void* d_out, int out_size)
{
    const int*   src   = (const int*)  d_in[0];
    const int*   tgt   = (const int*)  d_in[1];
    const float* embS  = (const float*)d_in[2];
    const float* embD  = (const float*)d_in[3];
    const float* eWih  = (const float*)d_in[4];
    const float* eWhh  = (const float*)d_in[5];
    const float* ebih  = (const float*)d_in[6];
    const float* ebhh  = (const float*)d_in[7];
    const float* d0Wih = (const float*)d_in[8];
    const float* d0Whh = (const float*)d_in[9];
    const float* d0bih = (const float*)d_in[10];
    const float* d0bhh = (const float*)d_in[11];
    const float* dWih  = (const float*)d_in[12];
    const float* dWhh  = (const float*)d_in[13];
    const float* dbih  = (const float*)d_in[14];
    const float* dbhh  = (const float*)d_in[15];
    const float* Wattn = (const float*)d_in[16];
    const float* Wcat  = (const float*)d_in[17];
    const float* bcat  = (const float*)d_in[18];
    const float* Wout  = (const float*)d_in[19];
    const float* bout  = (const float*)d_in[20];
    float* out = (float*)d_out;

    float* encx = sym(g_encx);  float* ency = sym(g_ency);
    float* encxg = sym(g_encxg);
    float* ehA = sym(g_enchA);  float* ehB = sym(g_enchB);
    float* ecc = sym(g_encc);
    float* h0 = sym(g_h0);      float* c0 = sym(g_c0);
    float* demb = sym(g_demb);  float* pre0 = sym(g_pre0);
    float* dhA = sym(g_dhA);    float* dhB = sym(g_dhB);
    float* dc  = sym(g_dc);
    float* htl = sym(g_htl);    float* ctx = sym(g_ctx);
    float* hAp = sym(g_hA);     float* hbt = sym(g_hbt);
    __nv_bfloat16* wbf = (__nv_bfloat16*)sym(g_wbf);
    __nv_bfloat16* wout = (__nv_bfloat16*)sym(g_wout);
    int* ctrs = (int*)sym(g_ctrs);

    static cudaStream_t s2 = nullptr;
    static cudaEvent_t evf, evpre;
    if (!s2) {
        cudaStreamCreateWithFlags(&s2, cudaStreamNonBlocking);
        cudaEventCreateWithFlags(&evf, cudaEventDisableTiming);
        cudaEventCreateWithFlags(&evpre, cudaEventDisableTiming);
    }

    ctrz_k<<<66, 256>>>();
    cudaEventRecord(evf, 0);
    cudaStreamWaitEvent(s2, evf, 0);

    // ---- precompute on s2 (overlaps encoder on s0) ----
    {
        long n1 = 4194304L, n3 = 12582912L, nc = 1048576L;
        cvt_k <<<1024, 256, 0, s2>>>(wbf + OFF_W0H, d0Wih, 2048, 1024, 1024, n1);
        cvtf_k<<<1024, 256, 0, s2>>>(wbf + OFF_W0R, d0Whh, n1/4);
        cvtf_k<<<2048, 256, 0, s2>>>(wbf + OFF_WIH, dWih, n3/4);
        cvtf_k<<<2048, 256, 0, s2>>>(wbf + OFF_WHH, dWhh, n3/4);
        cvt_k <<<512, 256, 0, s2>>>(wbf + OFF_WC1, Wcat, 2048, 0, 1024, nc);
        cvt_k <<<512, 256, 0, s2>>>(wbf + OFF_WC2, Wcat, 2048, 1024, 1024, nc);
        cvtf_k<<<2048, 256, 0, s2>>>(wout, Wout, (long)VOUT*HID/4);
        embed_k<<<dim3(TL, BA), 256, 0, s2>>>(tgt, embD, demb, TL);
        gemm_tc_k<<<dim3(32, 7), 256, 0, s2>>>(demb, HID, d0Wih, 2048, d0bih, d0bhh,
                                               pre0, 4096, TL*BA, 4096, 1024);
    }
    cudaEventRecord(evpre, s2);

    // ---- encoder on s0 (MMA step kernels) ----
    embed_k<<<dim3(SL, BA), 256>>>(src, embS, encx, SL);
    float* xin = encx; float* yout = ency;
    for (int l = 0; l < NL; l++) {
        gemm_tc_k<<<dim3(32, 7), 256>>>(xin, HID, eWih + (long)l*4096*1024, 1024,
                                        ebih + l*4096, ebhh + l*4096, encxg, 4096,
                                        SL*BA, 4096, 1024);
        float* hi = ehA; float* ho = ehB;
        const float* Whh = eWhh + (long)l*4096*512;
        for (int st = 0; st < SL; st++) {
            enc_mma_k<<<128, 256>>>(Whh, encxg, hi, ho, ecc, yout,
                                    h0 + (long)l*BA*HID, c0 + (long)l*BA*HID,
                                    st, ctrs + 10240 + (l*50 + st)*32);
            float* tmp = hi; hi = ho; ho = tmp;
        }
        float* t = xin; xin = yout; yout = t;
    }
    float* hsrc = xin;

    gemm_k<<<dim3(8, 7), 256>>>(hsrc, HID, Wattn, 1024, 0, hAp, HID,
                                SL*BA, 1024, 1024);
    dinit_k<<<NL*BA*HID/256, 256>>>(dhA, h0, dc, c0, htl);
    cudaStreamWaitEvent(0, evpre, 0);

    // ---- decoder loop: 5 kernels/step ----
    for (int t = 0; t < TL; t++) {
        float* hprev = (t & 1) ? dhB : dhA;
        float* hcur  = (t & 1) ? dhA : dhB;
        int base = t*5*40;
        mmbf_cell_k<<<512, 256>>>(wbf + OFF_W0H, wbf + OFF_W0R, htl, hprev,
                                  pre0 + (long)t*BA*4096, nullptr, nullptr,
                                  dc, hcur,
                                  ctrs + base, nullptr, nullptr, nullptr, nullptr);
        for (int i = 0; i < NL-1; i++) {
            int last = (i == NL-2);
            int b2 = base + (i+1)*40;
            mmbf_cell_k<<<512, 256>>>(wbf + OFF_WIH + (long)i*4194304,
                                      wbf + OFF_WHH + (long)i*4194304,
                                      hcur + (long)i*BA*HID,
                                      hprev + (long)(i+1)*BA*HID,
                                      nullptr, dbih + i*4096, dbhh + i*4096,
                                      dc + (long)(i+1)*BA*HID,
                                      hcur + (long)(i+1)*BA*HID,
                                      ctrs + b2,
                                      last ? (ctrs + b2 + 32) : nullptr,
                                      last ? hAp : nullptr,
                                      last ? hsrc : nullptr,
                                      last ? ctx : nullptr);
        }
        mmbf_ht_k<<<128, 256>>>(wbf + OFF_WC1, wbf + OFF_WC2,
                                hcur + (long)3*BA*HID, ctx,
                                bcat, htl, hbt, t, ctrs + base + 4*40);
    }

    // ---- generator (serial, bf16 weights) ----
    gemm_tcb_k<<<dim3(250, 7), 256>>>(hbt, HID, wout, 1024, bout,
                                      out, VOUT, TL*BA, VOUT, HID, 0);
    lsm_k<<<TL*BA, 256>>>(out);
}